// round 1
// baseline (speedup 1.0000x reference)
#include <cuda_runtime.h>
#include <math.h>

#define L_TOK 21952
#define C_DIM 384
#define C2    768
#define C4    1536
#define NHEAD 12
#define HD    32
#define NWIN  64
#define NTOK  343   // 7^3
#define KSTR  33    // padded shared stride for K/V tiles

// ---------------- scratch (device globals; no allocation allowed) ----------------
__device__ float g_X [L_TOK * C_DIM];            // running residual x
__device__ float g_SK[L_TOK * C_DIM];            // ln1(skip), window-partitioned
__device__ float g_QX[L_TOK * C_DIM];            // ln1(x_up), window-partitioned
__device__ float g_KV[(size_t)L_TOK * C2];       // kv projection, window order
__device__ float g_O [L_TOK * C_DIM];            // attention output, window order
__device__ float g_Y [L_TOK * C_DIM];            // ln2(x)
__device__ float g_H1[(size_t)L_TOK * C4];       // mlp hidden
__device__ float g_bias[NHEAD * NTOK * NTOK];    // expanded rel-pos bias [h][q][k]

// ---------------- kernel 1: x = skip + x_up ; LN1(skip)->SK ; LN1(x_up)->QX ----------------
// one block per token (128 threads, 3 channels each)
__global__ void add_ln1_kernel(const float* __restrict__ skip,
                               const float* __restrict__ xup,
                               const float* __restrict__ g,
                               const float* __restrict__ b)
{
    int l   = blockIdx.x;
    int tid = threadIdx.x;
    const float* srow = skip + (size_t)l * C_DIM;
    const float* urow = xup  + (size_t)l * C_DIM;

    float sv[3], uv[3];
    float ssum = 0.f, ssq = 0.f, usum = 0.f, usq = 0.f;
#pragma unroll
    for (int t = 0; t < 3; t++) {
        int c = tid + t * 128;
        float s = srow[c], u = urow[c];
        sv[t] = s; uv[t] = u;
        g_X[(size_t)l * C_DIM + c] = s + u;
        ssum += s; ssq += s * s; usum += u; usq += u * u;
    }
    // block reduce (4 warps)
    __shared__ float red[4][4];
#pragma unroll
    for (int o = 16; o > 0; o >>= 1) {
        ssum += __shfl_down_sync(0xffffffffu, ssum, o);
        ssq  += __shfl_down_sync(0xffffffffu, ssq , o);
        usum += __shfl_down_sync(0xffffffffu, usum, o);
        usq  += __shfl_down_sync(0xffffffffu, usq , o);
    }
    int warp = tid >> 5, lane = tid & 31;
    if (lane == 0) { red[warp][0]=ssum; red[warp][1]=ssq; red[warp][2]=usum; red[warp][3]=usq; }
    __syncthreads();
    float S  = red[0][0]+red[1][0]+red[2][0]+red[3][0];
    float SQ = red[0][1]+red[1][1]+red[2][1]+red[3][1];
    float U  = red[0][2]+red[1][2]+red[2][2]+red[3][2];
    float UQ = red[0][3]+red[1][3]+red[2][3]+red[3][3];
    const float inv = 1.f / (float)C_DIM;
    float ms = S * inv,  vs = SQ * inv - ms * ms;
    float mu = U * inv,  vu = UQ * inv - mu * mu;
    float rs = rsqrtf(vs + 1e-5f);
    float ru = rsqrtf(vu + 1e-5f);

    // window-partition mapping: linear token l -> window row
    int d = l / 784, rem = l % 784, hh = rem / 28, ww = rem % 28;
    int widx = ((d / 7) * 4 + hh / 7) * 4 + ww / 7;
    int nidx = ((d % 7) * 7 + hh % 7) * 7 + ww % 7;
    size_t wrow = (size_t)(widx * NTOK + nidx) * C_DIM;

#pragma unroll
    for (int t = 0; t < 3; t++) {
        int c = tid + t * 128;
        float gg = g[c], bb = b[c];
        g_SK[wrow + c] = (sv[t] - ms) * rs * gg + bb;
        g_QX[wrow + c] = (uv[t] - mu) * ru * gg + bb;
    }
}

// ---------------- kernel 2: expand relative position bias ----------------
__global__ void bias_kernel(const float* __restrict__ rpb)
{
    int i = blockIdx.x * blockDim.x + threadIdx.x;
    if (i >= NHEAD * NTOK * NTOK) return;
    int h = i / (NTOK * NTOK);
    int r = i % (NTOK * NTOK);
    int q = r / NTOK, k = r % NTOK;
    int z1 = q / 49, y1 = (q / 7) % 7, x1 = q % 7;
    int z2 = k / 49, y2 = (k / 7) % 7, x2 = k % 7;
    int rel = (z1 - z2 + 6) * 169 + (y1 - y2 + 6) * 13 + (x1 - x2 + 6);
    g_bias[i] = rpb[rel * NHEAD + h];
}

// ---------------- tiled SGEMM: C[M,N] = A[M,K] @ B[K,N] + bias, with epilogues ----------------
// EPI 0: plain store   1: proj (scatter-add into X with window reverse)
// EPI 2: gelu store    3: out = Xres + v
template <int EPI>
__global__ void sgemm_kernel(const float* __restrict__ A, const float* __restrict__ B,
                             const float* __restrict__ bias, float* __restrict__ Cout,
                             const float* __restrict__ Xres, int Ksz, int Nn)
{
    __shared__ float As[16][64];
    __shared__ float Bs[16][64];
    int tid = threadIdx.x;
    int rowBase = blockIdx.y * 64, colBase = blockIdx.x * 64;
    int ar = tid >> 2,  ac4 = (tid & 3) * 4;
    int br = tid >> 4,  bc4 = (tid & 15) * 4;
    int ty = tid >> 4,  tx  = tid & 15;
    float acc[4][4] = {};

    for (int k0 = 0; k0 < Ksz; k0 += 16) {
        float4 av = *(const float4*)(A + (size_t)(rowBase + ar) * Ksz + k0 + ac4);
        As[ac4 + 0][ar] = av.x; As[ac4 + 1][ar] = av.y;
        As[ac4 + 2][ar] = av.z; As[ac4 + 3][ar] = av.w;
        float4 bv = *(const float4*)(B + (size_t)(k0 + br) * Nn + colBase + bc4);
        *(float4*)&Bs[br][bc4] = bv;
        __syncthreads();
#pragma unroll
        for (int kk = 0; kk < 16; kk++) {
            float a[4], bb[4];
#pragma unroll
            for (int i = 0; i < 4; i++) a[i]  = As[kk][ty * 4 + i];
#pragma unroll
            for (int j = 0; j < 4; j++) bb[j] = Bs[kk][tx * 4 + j];
#pragma unroll
            for (int i = 0; i < 4; i++)
#pragma unroll
                for (int j = 0; j < 4; j++) acc[i][j] += a[i] * bb[j];
        }
        __syncthreads();
    }

#pragma unroll
    for (int i = 0; i < 4; i++) {
        int row  = rowBase + ty * 4 + i;
        int lrow = row;
        if (EPI == 1) { // window-reverse: window row -> linear token
            int widx = row / NTOK, n = row % NTOK;
            int dd =  (widx / 16)     * 7 + n / 49;
            int hh = ((widx / 4) % 4) * 7 + (n / 7) % 7;
            int ww =  (widx % 4)      * 7 + n % 7;
            lrow = (dd * 28 + hh) * 28 + ww;
        }
#pragma unroll
        for (int j = 0; j < 4; j++) {
            int col = colBase + tx * 4 + j;
            float v = acc[i][j] + bias[col];
            if (EPI == 0) {
                Cout[(size_t)row * Nn + col] = v;
            } else if (EPI == 1) {
                Cout[(size_t)lrow * Nn + col] += v;
            } else if (EPI == 2) {
                float t = tanhf(0.7978845608028654f * (v + 0.044715f * v * v * v));
                Cout[(size_t)row * Nn + col] = 0.5f * v * (1.f + t);
            } else {
                Cout[(size_t)row * Nn + col] = Xres[(size_t)row * Nn + col] + v;
            }
        }
    }
}

// ---------------- kernel: attention per (window, head) ----------------
// smem: K tile [343][33], V tile [343][33], probs [8 warps][343]
__global__ void attn_kernel()
{
    extern __shared__ float sm[];
    float* k_s = sm;
    float* v_s = sm + NTOK * KSTR;
    float* p_s = v_s + NTOK * KSTR;

    int w = blockIdx.x / NHEAD;
    int h = blockIdx.x % NHEAD;
    int tid = threadIdx.x;

    // stage K,V for this (window, head)
    for (int i = tid; i < NTOK * HD; i += 256) {
        int n = i >> 5, d = i & 31;
        const float* r = g_KV + (size_t)(w * NTOK + n) * C2 + h * HD + d;
        k_s[n * KSTR + d] = r[0];
        v_s[n * KSTR + d] = r[C_DIM];
    }
    __syncthreads();

    int warp = tid >> 5, lane = tid & 31;
    float* p = p_s + warp * NTOK;
    const float scale = 0.17677669529663687f; // 1/sqrt(32)
    const float* biasbase = g_bias + (size_t)h * NTOK * NTOK;

    for (int q = warp; q < NTOK; q += 8) {
        float qv[HD];
        const float* qrow = g_QX + (size_t)(w * NTOK + q) * C_DIM + h * HD;
#pragma unroll
        for (int d = 0; d < HD; d++) qv[d] = qrow[d] * scale;

        const float* brow = biasbase + (size_t)q * NTOK;
        float sloc[11];
        float mmax = -1e30f;
#pragma unroll
        for (int j = 0; j < 11; j++) {
            int k0 = lane + j * 32;
            float s = -1e30f;
            if (k0 < NTOK) {
                s = brow[k0];
                const float* kr = k_s + k0 * KSTR;
#pragma unroll
                for (int d = 0; d < HD; d++) s += qv[d] * kr[d];
            }
            sloc[j] = s;
            mmax = fmaxf(mmax, s);
        }
#pragma unroll
        for (int o = 16; o > 0; o >>= 1)
            mmax = fmaxf(mmax, __shfl_xor_sync(0xffffffffu, mmax, o));
        float lsum = 0.f;
#pragma unroll
        for (int j = 0; j < 11; j++) {
            int k0 = lane + j * 32;
            if (k0 < NTOK) {
                float e = __expf(sloc[j] - mmax);
                p[k0] = e;
                lsum += e;
            }
        }
#pragma unroll
        for (int o = 16; o > 0; o >>= 1)
            lsum += __shfl_xor_sync(0xffffffffu, lsum, o);
        float inv = 1.f / lsum;
        __syncwarp();

        // PV: lane owns output channel = lane
        float acc = 0.f;
        for (int k = 0; k < NTOK; k++)
            acc += p[k] * v_s[k * KSTR + lane];
        g_O[(size_t)(w * NTOK + q) * C_DIM + h * HD + lane] = acc * inv;
        __syncwarp();
    }
}

// ---------------- kernel: LN2 ----------------
__global__ void ln2_kernel(const float* __restrict__ g, const float* __restrict__ b)
{
    int l = blockIdx.x;
    int tid = threadIdx.x;
    const float* row = g_X + (size_t)l * C_DIM;
    float xv[3];
    float s = 0.f, sq = 0.f;
#pragma unroll
    for (int t = 0; t < 3; t++) {
        int c = tid + t * 128;
        float x = row[c];
        xv[t] = x; s += x; sq += x * x;
    }
    __shared__ float red[4][2];
#pragma unroll
    for (int o = 16; o > 0; o >>= 1) {
        s  += __shfl_down_sync(0xffffffffu, s , o);
        sq += __shfl_down_sync(0xffffffffu, sq, o);
    }
    int warp = tid >> 5, lane = tid & 31;
    if (lane == 0) { red[warp][0] = s; red[warp][1] = sq; }
    __syncthreads();
    float S  = red[0][0]+red[1][0]+red[2][0]+red[3][0];
    float SQ = red[0][1]+red[1][1]+red[2][1]+red[3][1];
    const float inv = 1.f / (float)C_DIM;
    float m = S * inv;
    float rs = rsqrtf(SQ * inv - m * m + 1e-5f);
#pragma unroll
    for (int t = 0; t < 3; t++) {
        int c = tid + t * 128;
        g_Y[(size_t)l * C_DIM + c] = (xv[t] - m) * rs * g[c] + b[c];
    }
}

// ---------------- launch ----------------
extern "C" void kernel_launch(void* const* d_in, const int* in_sizes, int n_in,
                              void* d_out, int out_size)
{
    const float* skip  = (const float*)d_in[0];
    const float* x_up  = (const float*)d_in[1];
    // D,H,W may appear as scalar inputs at indices 2..4
    int o = (n_in >= 18) ? 5 : 2;
    const float* ln1_g  = (const float*)d_in[o + 0];
    const float* ln1_b  = (const float*)d_in[o + 1];
    const float* kv_w   = (const float*)d_in[o + 2];
    const float* kv_b   = (const float*)d_in[o + 3];
    const float* rpb    = (const float*)d_in[o + 4];
    const float* proj_w = (const float*)d_in[o + 5];
    const float* proj_b = (const float*)d_in[o + 6];
    const float* ln2_g  = (const float*)d_in[o + 7];
    const float* ln2_b  = (const float*)d_in[o + 8];
    const float* mlp_w1 = (const float*)d_in[o + 9];
    const float* mlp_b1 = (const float*)d_in[o + 10];
    const float* mlp_w2 = (const float*)d_in[o + 11];
    const float* mlp_b2 = (const float*)d_in[o + 12];
    float* out = (float*)d_out;

    float *pX, *pSK, *pQX, *pKV, *pO, *pY, *pH1;
    cudaGetSymbolAddress((void**)&pX , g_X );
    cudaGetSymbolAddress((void**)&pSK, g_SK);
    cudaGetSymbolAddress((void**)&pQX, g_QX);
    cudaGetSymbolAddress((void**)&pKV, g_KV);
    cudaGetSymbolAddress((void**)&pO , g_O );
    cudaGetSymbolAddress((void**)&pY , g_Y );
    cudaGetSymbolAddress((void**)&pH1, g_H1);

    int attn_smem = (2 * NTOK * KSTR + 8 * NTOK) * (int)sizeof(float); // ~101.5 KB
    cudaFuncSetAttribute(attn_kernel, cudaFuncAttributeMaxDynamicSharedMemorySize, attn_smem);

    // 1. residual add + LN1s (window-partitioned outputs)
    add_ln1_kernel<<<L_TOK, 128>>>(skip, x_up, ln1_g, ln1_b);
    // 2. bias table
    bias_kernel<<<(NHEAD * NTOK * NTOK + 255) / 256, 256>>>(rpb);
    // 3. KV projection: [21952,384] @ [384,768]
    sgemm_kernel<0><<<dim3(C2 / 64, L_TOK / 64), 256>>>(pSK, kv_w, kv_b, pKV, nullptr, C_DIM, C2);
    // 4. attention per (window, head)
    attn_kernel<<<NWIN * NHEAD, 256, attn_smem>>>();
    // 5. proj + scatter-add residual into X (window reverse)
    sgemm_kernel<1><<<dim3(C_DIM / 64, L_TOK / 64), 256>>>(pO, proj_w, proj_b, pX, nullptr, C_DIM, C_DIM);
    // 6. LN2
    ln2_kernel<<<L_TOK, 128>>>(ln2_g, ln2_b);
    // 7. MLP1 + GELU: [21952,384] @ [384,1536]
    sgemm_kernel<2><<<dim3(C4 / 64, L_TOK / 64), 256>>>(pY, mlp_w1, mlp_b1, pH1, nullptr, C_DIM, C4);
    // 8. MLP2 + residual -> out: [21952,1536] @ [1536,384]
    sgemm_kernel<3><<<dim3(C_DIM / 64, L_TOK / 64), 256>>>(pH1, mlp_w2, mlp_b2, out, pX, C4, C_DIM);
}

// round 5
// speedup vs baseline: 1.5420x; 1.5420x over previous
#include <cuda_runtime.h>
#include <cuda_bf16.h>
#include <math.h>
#include <stdint.h>

#define L_TOK 21952
#define MPAD  22016
#define C_DIM 384
#define C2    768
#define C4    1536
#define NHEAD 12
#define HD    32
#define NWIN  64
#define NTOK  343
#define KSTR  33

// ---------------- scratch (device globals) ----------------
__device__ float g_X [(size_t)L_TOK * C_DIM];
__device__ float g_QX[(size_t)L_TOK * C_DIM];
__device__ float g_KV[(size_t)MPAD * C2];
__device__ __nv_bfloat16 g_SKh[(size_t)MPAD * C_DIM], g_SKl[(size_t)MPAD * C_DIM];
__device__ __nv_bfloat16 g_Oh [(size_t)MPAD * C_DIM], g_Ol [(size_t)MPAD * C_DIM];
__device__ __nv_bfloat16 g_Yh [(size_t)MPAD * C_DIM], g_Yl [(size_t)MPAD * C_DIM];
__device__ __nv_bfloat16 g_H1h[(size_t)MPAD * C4],    g_H1l[(size_t)MPAD * C4];
__device__ float g_bias[NHEAD * NTOK * NTOK];
// weights transposed to [N][K] row-major, split hi/lo
__device__ __nv_bfloat16 g_Wkvh[C2 * C_DIM],    g_Wkvl[C2 * C_DIM];
__device__ __nv_bfloat16 g_Wprh[C_DIM * C_DIM], g_Wprl[C_DIM * C_DIM];
__device__ __nv_bfloat16 g_W1h [C4 * C_DIM],    g_W1l [C4 * C_DIM];
__device__ __nv_bfloat16 g_W2h [C_DIM * C4],    g_W2l [C_DIM * C4];

// ---------------- helpers ----------------
__device__ __forceinline__ uint32_t smem_u32(const void* p) {
    uint32_t a;
    asm("{ .reg .u64 t; cvta.to.shared.u64 t, %1; cvt.u32.u64 %0, t; }" : "=r"(a) : "l"(p));
    return a;
}
__device__ __forceinline__ void bsplit(float v, __nv_bfloat16& h, __nv_bfloat16& l) {
    h = __float2bfloat16(v);
    l = __float2bfloat16(v - __bfloat162float(h));
}

// swizzled smem offset for a [128 x 32] bf16 tile (row = 64B = 4 x 16B chunks)
// injective over 8-row x 16B-slot groups -> conflict-free STS.128 and ldmatrix
__device__ __forceinline__ uint32_t swz(uint32_t row, uint32_t c) {
    return row * 64u + ((c ^ ((row >> 1) & 3u)) << 4);
}
__device__ __forceinline__ void cp16(uint32_t sm, const void* gm) {
    asm volatile("cp.async.cg.shared.global [%0], [%1], 16;" :: "r"(sm), "l"(gm));
}
#define CP_COMMIT() asm volatile("cp.async.commit_group;" ::: "memory")

#define LDMX4(r0, r1, r2, r3, addr) \
    asm volatile("ldmatrix.sync.aligned.m8n8.x4.shared.b16 {%0,%1,%2,%3}, [%4];" \
        : "=r"(r0), "=r"(r1), "=r"(r2), "=r"(r3) : "r"(addr))

#define MMA16816(d, a, b) \
    asm volatile("mma.sync.aligned.m16n8k16.row.col.f32.bf16.bf16.f32 " \
        "{%0,%1,%2,%3}, {%4,%5,%6,%7}, {%8,%9}, {%0,%1,%2,%3};" \
        : "+f"((d)[0]), "+f"((d)[1]), "+f"((d)[2]), "+f"((d)[3]) \
        : "r"((a)[0]), "r"((a)[1]), "r"((a)[2]), "r"((a)[3]), \
          "r"((b)[0]), "r"((b)[1]))

// ---------------- kernel 1: x = skip + x_up ; LN1(skip)->SKh/l ; LN1(x_up)->QX ----------------
__global__ void add_ln1_kernel(const float* __restrict__ skip,
                               const float* __restrict__ xup,
                               const float* __restrict__ g,
                               const float* __restrict__ b)
{
    int l = blockIdx.x, tid = threadIdx.x;
    const float* srow = skip + (size_t)l * C_DIM;
    const float* urow = xup  + (size_t)l * C_DIM;
    float sv[3], uv[3];
    float ssum = 0.f, ssq = 0.f, usum = 0.f, usq = 0.f;
#pragma unroll
    for (int t = 0; t < 3; t++) {
        int c = tid + t * 128;
        float s = srow[c], u = urow[c];
        sv[t] = s; uv[t] = u;
        g_X[(size_t)l * C_DIM + c] = s + u;
        ssum += s; ssq += s * s; usum += u; usq += u * u;
    }
    __shared__ float red[4][4];
#pragma unroll
    for (int o = 16; o > 0; o >>= 1) {
        ssum += __shfl_down_sync(0xffffffffu, ssum, o);
        ssq  += __shfl_down_sync(0xffffffffu, ssq , o);
        usum += __shfl_down_sync(0xffffffffu, usum, o);
        usq  += __shfl_down_sync(0xffffffffu, usq , o);
    }
    int warp = tid >> 5, lane = tid & 31;
    if (lane == 0) { red[warp][0]=ssum; red[warp][1]=ssq; red[warp][2]=usum; red[warp][3]=usq; }
    __syncthreads();
    float S  = red[0][0]+red[1][0]+red[2][0]+red[3][0];
    float SQ = red[0][1]+red[1][1]+red[2][1]+red[3][1];
    float U  = red[0][2]+red[1][2]+red[2][2]+red[3][2];
    float UQ = red[0][3]+red[1][3]+red[2][3]+red[3][3];
    const float inv = 1.f / (float)C_DIM;
    float ms = S * inv, vs = SQ * inv - ms * ms;
    float mu = U * inv, vu = UQ * inv - mu * mu;
    float rs = rsqrtf(vs + 1e-5f), ru = rsqrtf(vu + 1e-5f);

    int d = l / 784, rem = l % 784, hh = rem / 28, ww = rem % 28;
    int widx = ((d / 7) * 4 + hh / 7) * 4 + ww / 7;
    int nidx = ((d % 7) * 7 + hh % 7) * 7 + ww % 7;
    size_t wrow = (size_t)(widx * NTOK + nidx) * C_DIM;
#pragma unroll
    for (int t = 0; t < 3; t++) {
        int c = tid + t * 128;
        float gg = g[c], bb = b[c];
        float skv = (sv[t] - ms) * rs * gg + bb;
        __nv_bfloat16 h, lo; bsplit(skv, h, lo);
        g_SKh[wrow + c] = h; g_SKl[wrow + c] = lo;
        g_QX[wrow + c] = (uv[t] - mu) * ru * gg + bb;
    }
}

// ---------------- kernel 2: expand relative position bias ----------------
__global__ void bias_kernel(const float* __restrict__ rpb)
{
    int i = blockIdx.x * blockDim.x + threadIdx.x;
    if (i >= NHEAD * NTOK * NTOK) return;
    int h = i / (NTOK * NTOK);
    int r = i % (NTOK * NTOK);
    int q = r / NTOK, k = r % NTOK;
    int z1 = q / 49, y1 = (q / 7) % 7, x1 = q % 7;
    int z2 = k / 49, y2 = (k / 7) % 7, x2 = k % 7;
    int rel = (z1 - z2 + 6) * 169 + (y1 - y2 + 6) * 13 + (x1 - x2 + 6);
    g_bias[i] = rpb[rel * NHEAD + h];
}

// ---------------- weight prep: W[K][N] fp32 -> Wt_hi/lo [N][K] bf16 ----------------
__global__ void wprep_kernel(const float* __restrict__ W,
                             __nv_bfloat16* __restrict__ Th,
                             __nv_bfloat16* __restrict__ Tl, int K, int N)
{
    int i = blockIdx.x * blockDim.x + threadIdx.x;
    if (i >= K * N) return;
    int n = i / K, k = i % K;
    float w = W[(size_t)k * N + n];
    __nv_bfloat16 h, lo; bsplit(w, h, lo);
    Th[i] = h; Tl[i] = lo;
}

// ---------------- mma.sync GEMM: C[M,N] = A @ Bt^T  (Bt is [N][K]) ----------------
// split-compensated bf16: D = Ah*Bh + Ah*Bl + Al*Bh (fp32 accumulate)
// EPI 0: KV fp32 store     1: proj scatter-add residual into g_X (window reverse)
// EPI 2: gelu -> bf16 hi/lo 3: out = Xres + v (bounded)
#define GBM 128
#define GBN 128
#define GBK 32
#define STAGE 32768   // Ah 8K | Al 8K | Bh 8K | Bl 8K

template <int EPI>
__global__ void __launch_bounds__(256)
hmma_gemm(const __nv_bfloat16* __restrict__ Ah, const __nv_bfloat16* __restrict__ Al,
          const __nv_bfloat16* __restrict__ Bh, const __nv_bfloat16* __restrict__ Bl,
          const float* __restrict__ bias, float* __restrict__ Cf,
          __nv_bfloat16* __restrict__ Ch, __nv_bfloat16* __restrict__ Cl,
          const float* __restrict__ Xres, int K, int N, int Mvalid)
{
    extern __shared__ char smem[];
    const int tid = threadIdx.x, lane = tid & 31, wid = tid >> 5;
    const int rowBase = blockIdx.y * GBM, colBase = blockIdx.x * GBN;
    const int wM = (wid & 3) * 32, wN = (wid >> 2) * 64;
    const uint32_t sbase = smem_u32(smem);

    float acc[2][8][4];
#pragma unroll
    for (int m = 0; m < 2; m++)
#pragma unroll
        for (int n = 0; n < 8; n++)
#pragma unroll
            for (int v = 0; v < 4; v++) acc[m][n][v] = 0.f;

    const int NC = K / GBK;

    // cp.async issue for chunk ch: each thread moves 2x16B per buffer
    auto issue = [&](int ch) {
        uint32_t sb = sbase + (ch & 1) * STAGE;
        int k0 = ch * GBK;
#pragma unroll
        for (int i = 0; i < 2; i++) {
            int ci = tid + i * 256;
            int r = ci >> 2, c = ci & 3;
            uint32_t so = swz(r, c);
            size_t aoff = (size_t)(rowBase + r) * K + k0 + c * 8;
            size_t boff = (size_t)(colBase + r) * K + k0 + c * 8;
            cp16(sb +         so, Ah + aoff);
            cp16(sb +  8192 + so, Al + aoff);
            cp16(sb + 16384 + so, Bh + boff);
            cp16(sb + 24576 + so, Bl + boff);
        }
        CP_COMMIT();
    };

    issue(0);
    for (int ch = 0; ch < NC; ch++) {
        if (ch + 1 < NC) {
            issue(ch + 1);
            asm volatile("cp.async.wait_group 1;" ::: "memory");
        } else {
            asm volatile("cp.async.wait_group 0;" ::: "memory");
        }
        __syncthreads();
        uint32_t sb = sbase + (ch & 1) * STAGE;

#pragma unroll
        for (int ks = 0; ks < 2; ks++) {
            uint32_t aH[2][4], aL[2][4];
#pragma unroll
            for (int m = 0; m < 2; m++) {
                uint32_t row = wM + m * 16 + (lane & 15);
                uint32_t c = ks * 2 + (lane >> 4);
                uint32_t ad = sb + swz(row, c);
                LDMX4(aH[m][0], aH[m][1], aH[m][2], aH[m][3], ad);
                LDMX4(aL[m][0], aL[m][1], aL[m][2], aL[m][3], ad + 8192);
            }
            uint32_t bH[8][2], bL[8][2];
#pragma unroll
            for (int nb = 0; nb < 4; nb++) {
                uint32_t row = wN + nb * 16 + (lane & 7) + ((lane >> 4) & 1) * 8;
                uint32_t c = ks * 2 + ((lane >> 3) & 1);
                uint32_t bd = sb + 16384 + swz(row, c);
                LDMX4(bH[nb*2][0], bH[nb*2][1], bH[nb*2+1][0], bH[nb*2+1][1], bd);
                LDMX4(bL[nb*2][0], bL[nb*2][1], bL[nb*2+1][0], bL[nb*2+1][1], bd + 8192);
            }
#pragma unroll
            for (int m = 0; m < 2; m++)
#pragma unroll
                for (int n = 0; n < 8; n++) {
                    MMA16816(acc[m][n], aH[m], bH[n]);
                    MMA16816(acc[m][n], aH[m], bL[n]);
                    MMA16816(acc[m][n], aL[m], bH[n]);
                }
        }
        __syncthreads();
    }

    // ---------------- epilogue ----------------
    const int gid = lane >> 2, tig = lane & 3;
#pragma unroll
    for (int m = 0; m < 2; m++) {
#pragma unroll
        for (int rr = 0; rr < 2; rr++) {
            int row = rowBase + wM + m * 16 + gid + rr * 8;
            if (EPI == 0) {
#pragma unroll
                for (int n = 0; n < 8; n++) {
                    int col = colBase + wN + n * 8 + tig * 2;
                    float2 v;
                    v.x = acc[m][n][rr * 2 + 0] + bias[col];
                    v.y = acc[m][n][rr * 2 + 1] + bias[col + 1];
                    *(float2*)(Cf + (size_t)row * N + col) = v;
                }
            } else if (EPI == 1) {
                if (row < Mvalid) {
                    int widx = row / NTOK, nn = row % NTOK;
                    int dd =  (widx >> 4)      * 7 + nn / 49;
                    int hh = ((widx >> 2) & 3) * 7 + (nn / 7) % 7;
                    int ww =  (widx & 3)       * 7 + nn % 7;
                    int lrow = (dd * 28 + hh) * 28 + ww;
#pragma unroll
                    for (int n = 0; n < 8; n++) {
                        int col = colBase + wN + n * 8 + tig * 2;
                        float* p = Cf + (size_t)lrow * N + col;
                        p[0] += acc[m][n][rr * 2 + 0] + bias[col];
                        p[1] += acc[m][n][rr * 2 + 1] + bias[col + 1];
                    }
                }
            } else if (EPI == 2) {
#pragma unroll
                for (int n = 0; n < 8; n++) {
                    int col = colBase + wN + n * 8 + tig * 2;
#pragma unroll
                    for (int j = 0; j < 2; j++) {
                        float v = acc[m][n][rr * 2 + j] + bias[col + j];
                        float t = tanhf(0.7978845608028654f * (v + 0.044715f * v * v * v));
                        float gv = 0.5f * v * (1.f + t);
                        __nv_bfloat16 h, lo; bsplit(gv, h, lo);
                        Ch[(size_t)row * N + col + j] = h;
                        Cl[(size_t)row * N + col + j] = lo;
                    }
                }
            } else {
                if (row < Mvalid) {
#pragma unroll
                    for (int n = 0; n < 8; n++) {
                        int col = colBase + wN + n * 8 + tig * 2;
                        const float* xr = Xres + (size_t)row * N + col;
                        float2 v;
                        v.x = xr[0] + acc[m][n][rr * 2 + 0] + bias[col];
                        v.y = xr[1] + acc[m][n][rr * 2 + 1] + bias[col + 1];
                        *(float2*)(Cf + (size_t)row * N + col) = v;
                    }
                }
            }
        }
    }
}

// ---------------- attention per (window, head) — fp32 ----------------
__global__ void attn_kernel()
{
    extern __shared__ float sm[];
    float* k_s = sm;
    float* v_s = sm + NTOK * KSTR;
    float* p_s = v_s + NTOK * KSTR;

    int w = blockIdx.x / NHEAD;
    int h = blockIdx.x % NHEAD;
    int tid = threadIdx.x;

    for (int i = tid; i < NTOK * HD; i += 256) {
        int n = i >> 5, d = i & 31;
        const float* rr = g_KV + (size_t)(w * NTOK + n) * C2 + h * HD + d;
        k_s[n * KSTR + d] = rr[0];
        v_s[n * KSTR + d] = rr[C_DIM];
    }
    __syncthreads();

    int warp = tid >> 5, lane = tid & 31;
    float* p = p_s + warp * NTOK;
    const float scale = 0.17677669529663687f;
    const float* biasbase = g_bias + (size_t)h * NTOK * NTOK;

    for (int q = warp; q < NTOK; q += 8) {
        float qv[HD];
        const float* qrow = g_QX + (size_t)(w * NTOK + q) * C_DIM + h * HD;
#pragma unroll
        for (int d = 0; d < HD; d++) qv[d] = qrow[d] * scale;

        const float* brow = biasbase + (size_t)q * NTOK;
        float sloc[11];
        float mmax = -1e30f;
#pragma unroll
        for (int j = 0; j < 11; j++) {
            int k0 = lane + j * 32;
            float s = -1e30f;
            if (k0 < NTOK) {
                s = brow[k0];
                const float* kr = k_s + k0 * KSTR;
#pragma unroll
                for (int d = 0; d < HD; d++) s += qv[d] * kr[d];
            }
            sloc[j] = s;
            mmax = fmaxf(mmax, s);
        }
#pragma unroll
        for (int o = 16; o > 0; o >>= 1)
            mmax = fmaxf(mmax, __shfl_xor_sync(0xffffffffu, mmax, o));
        float lsum = 0.f;
#pragma unroll
        for (int j = 0; j < 11; j++) {
            int k0 = lane + j * 32;
            if (k0 < NTOK) {
                float e = __expf(sloc[j] - mmax);
                p[k0] = e;
                lsum += e;
            }
        }
#pragma unroll
        for (int o = 16; o > 0; o >>= 1)
            lsum += __shfl_xor_sync(0xffffffffu, lsum, o);
        float inv = 1.f / lsum;
        __syncwarp();

        float acc = 0.f;
        for (int k = 0; k < NTOK; k++)
            acc += p[k] * v_s[k * KSTR + lane];
        float o = acc * inv;
        size_t oi = (size_t)(w * NTOK + q) * C_DIM + h * HD + lane;
        __nv_bfloat16 hb, lb; bsplit(o, hb, lb);
        g_Oh[oi] = hb; g_Ol[oi] = lb;
        __syncwarp();
    }
}

// ---------------- LN2 -> Yh/Yl ----------------
__global__ void ln2_kernel(const float* __restrict__ g, const float* __restrict__ b)
{
    int l = blockIdx.x, tid = threadIdx.x;
    const float* row = g_X + (size_t)l * C_DIM;
    float xv[3];
    float s = 0.f, sq = 0.f;
#pragma unroll
    for (int t = 0; t < 3; t++) {
        int c = tid + t * 128;
        float x = row[c];
        xv[t] = x; s += x; sq += x * x;
    }
    __shared__ float red[4][2];
#pragma unroll
    for (int o = 16; o > 0; o >>= 1) {
        s  += __shfl_down_sync(0xffffffffu, s , o);
        sq += __shfl_down_sync(0xffffffffu, sq, o);
    }
    int warp = tid >> 5, lane = tid & 31;
    if (lane == 0) { red[warp][0] = s; red[warp][1] = sq; }
    __syncthreads();
    float S  = red[0][0]+red[1][0]+red[2][0]+red[3][0];
    float SQ = red[0][1]+red[1][1]+red[2][1]+red[3][1];
    const float inv = 1.f / (float)C_DIM;
    float m = S * inv;
    float rs = rsqrtf(SQ * inv - m * m + 1e-5f);
#pragma unroll
    for (int t = 0; t < 3; t++) {
        int c = tid + t * 128;
        float y = (xv[t] - m) * rs * g[c] + b[c];
        __nv_bfloat16 h, lo; bsplit(y, h, lo);
        g_Yh[(size_t)l * C_DIM + c] = h;
        g_Yl[(size_t)l * C_DIM + c] = lo;
    }
}

// ---------------- launch ----------------
extern "C" void kernel_launch(void* const* d_in, const int* in_sizes, int n_in,
                              void* d_out, int out_size)
{
    const float* skip = (const float*)d_in[0];
    const float* x_up = (const float*)d_in[1];
    int o = (n_in >= 18) ? 5 : 2;
    const float* ln1_g  = (const float*)d_in[o + 0];
    const float* ln1_b  = (const float*)d_in[o + 1];
    const float* kv_w   = (const float*)d_in[o + 2];
    const float* kv_b   = (const float*)d_in[o + 3];
    const float* rpb    = (const float*)d_in[o + 4];
    const float* proj_w = (const float*)d_in[o + 5];
    const float* proj_b = (const float*)d_in[o + 6];
    const float* ln2_g  = (const float*)d_in[o + 7];
    const float* ln2_b  = (const float*)d_in[o + 8];
    const float* mlp_w1 = (const float*)d_in[o + 9];
    const float* mlp_b1 = (const float*)d_in[o + 10];
    const float* mlp_w2 = (const float*)d_in[o + 11];
    const float* mlp_b2 = (const float*)d_in[o + 12];
    float* out = (float*)d_out;

    float *pX, *pKV;
    __nv_bfloat16 *pSKh, *pSKl, *pOh, *pOl, *pYh, *pYl, *pH1h, *pH1l;
    __nv_bfloat16 *pWkvh, *pWkvl, *pWprh, *pWprl, *pW1h, *pW1l, *pW2h, *pW2l;
    cudaGetSymbolAddress((void**)&pX,   g_X);
    cudaGetSymbolAddress((void**)&pKV,  g_KV);
    cudaGetSymbolAddress((void**)&pSKh, g_SKh); cudaGetSymbolAddress((void**)&pSKl, g_SKl);
    cudaGetSymbolAddress((void**)&pOh,  g_Oh);  cudaGetSymbolAddress((void**)&pOl,  g_Ol);
    cudaGetSymbolAddress((void**)&pYh,  g_Yh);  cudaGetSymbolAddress((void**)&pYl,  g_Yl);
    cudaGetSymbolAddress((void**)&pH1h, g_H1h); cudaGetSymbolAddress((void**)&pH1l, g_H1l);
    cudaGetSymbolAddress((void**)&pWkvh, g_Wkvh); cudaGetSymbolAddress((void**)&pWkvl, g_Wkvl);
    cudaGetSymbolAddress((void**)&pWprh, g_Wprh); cudaGetSymbolAddress((void**)&pWprl, g_Wprl);
    cudaGetSymbolAddress((void**)&pW1h,  g_W1h);  cudaGetSymbolAddress((void**)&pW1l,  g_W1l);
    cudaGetSymbolAddress((void**)&pW2h,  g_W2h);  cudaGetSymbolAddress((void**)&pW2l,  g_W2l);

    int gemm_smem = 2 * STAGE;  // 64 KB
    cudaFuncSetAttribute(hmma_gemm<0>, cudaFuncAttributeMaxDynamicSharedMemorySize, gemm_smem);
    cudaFuncSetAttribute(hmma_gemm<1>, cudaFuncAttributeMaxDynamicSharedMemorySize, gemm_smem);
    cudaFuncSetAttribute(hmma_gemm<2>, cudaFuncAttributeMaxDynamicSharedMemorySize, gemm_smem);
    cudaFuncSetAttribute(hmma_gemm<3>, cudaFuncAttributeMaxDynamicSharedMemorySize, gemm_smem);
    int attn_smem = (2 * NTOK * KSTR + 8 * NTOK) * (int)sizeof(float);
    cudaFuncSetAttribute(attn_kernel, cudaFuncAttributeMaxDynamicSharedMemorySize, attn_smem);

    const int MT = MPAD / GBM;  // 172

    add_ln1_kernel<<<L_TOK, 128>>>(skip, x_up, ln1_g, ln1_b);
    bias_kernel<<<(NHEAD * NTOK * NTOK + 255) / 256, 256>>>(rpb);
    wprep_kernel<<<(C_DIM * C2 + 255) / 256, 256>>>(kv_w,   pWkvh, pWkvl, C_DIM, C2);
    wprep_kernel<<<(C_DIM * C_DIM + 255) / 256, 256>>>(proj_w, pWprh, pWprl, C_DIM, C_DIM);
    wprep_kernel<<<(C_DIM * C4 + 255) / 256, 256>>>(mlp_w1, pW1h, pW1l, C_DIM, C4);
    wprep_kernel<<<(C4 * C_DIM + 255) / 256, 256>>>(mlp_w2, pW2h, pW2l, C4, C_DIM);
    // KV projection [Mpad,384]@[384,768]
    hmma_gemm<0><<<dim3(C2 / GBN, MT), 256, gemm_smem>>>(pSKh, pSKl, pWkvh, pWkvl,
        kv_b, pKV, nullptr, nullptr, nullptr, C_DIM, C2, L_TOK);
    // attention
    attn_kernel<<<NWIN * NHEAD, 256, attn_smem>>>();
    // proj + scatter-add residual into X
    hmma_gemm<1><<<dim3(C_DIM / GBN, MT), 256, gemm_smem>>>(pOh, pOl, pWprh, pWprl,
        proj_b, pX, nullptr, nullptr, nullptr, C_DIM, C_DIM, L_TOK);
    // LN2 -> Yh/Yl
    ln2_kernel<<<L_TOK, 128>>>(ln2_g, ln2_b);
    // MLP1 + GELU -> H1 bf16 hi/lo
    hmma_gemm<2><<<dim3(C4 / GBN, MT), 256, gemm_smem>>>(pYh, pYl, pW1h, pW1l,
        mlp_b1, nullptr, pH1h, pH1l, nullptr, C_DIM, C4, L_TOK);
    // MLP2 + residual -> out
    hmma_gemm<3><<<dim3(C_DIM / GBN, MT), 256, gemm_smem>>>(pH1h, pH1l, pW2h, pW2l,
        mlp_b2, out, nullptr, nullptr, pX, C4, C_DIM, L_TOK);
}

// round 6
// speedup vs baseline: 2.5859x; 1.6770x over previous
#include <cuda_runtime.h>
#include <cuda_bf16.h>
#include <math.h>
#include <stdint.h>

#define L_TOK 21952
#define MPAD  22016
#define C_DIM 384
#define C2    768
#define C4    1536
#define NHEAD 12
#define HD    32
#define NWIN  64
#define NTOK  343
#define BSTR  344   // padded bias row stride

// ---------------- scratch (device globals) ----------------
__device__ float g_X [(size_t)L_TOK * C_DIM];
__device__ __nv_bfloat16 g_Qh [(size_t)L_TOK * C_DIM], g_Ql [(size_t)L_TOK * C_DIM];
__device__ __nv_bfloat16 g_KVh[(size_t)MPAD * C2],     g_KVl[(size_t)MPAD * C2];
__device__ __nv_bfloat16 g_SKh[(size_t)MPAD * C_DIM],  g_SKl[(size_t)MPAD * C_DIM];
__device__ __nv_bfloat16 g_Oh [(size_t)MPAD * C_DIM],  g_Ol [(size_t)MPAD * C_DIM];
__device__ __nv_bfloat16 g_Yh [(size_t)MPAD * C_DIM],  g_Yl [(size_t)MPAD * C_DIM];
__device__ __nv_bfloat16 g_H1h[(size_t)MPAD * C4],     g_H1l[(size_t)MPAD * C4];
__device__ float g_bias[NHEAD * NTOK * BSTR];
// weights transposed to [N][K] row-major, split hi/lo
__device__ __nv_bfloat16 g_Wkvh[C2 * C_DIM],    g_Wkvl[C2 * C_DIM];
__device__ __nv_bfloat16 g_Wprh[C_DIM * C_DIM], g_Wprl[C_DIM * C_DIM];
__device__ __nv_bfloat16 g_W1h [C4 * C_DIM],    g_W1l [C4 * C_DIM];
__device__ __nv_bfloat16 g_W2h [C_DIM * C4],    g_W2l [C_DIM * C4];

// ---------------- helpers ----------------
__device__ __forceinline__ uint32_t smem_u32(const void* p) {
    uint32_t a;
    asm("{ .reg .u64 t; cvta.to.shared.u64 t, %1; cvt.u32.u64 %0, t; }" : "=r"(a) : "l"(p));
    return a;
}
__device__ __forceinline__ void bsplit(float v, __nv_bfloat16& h, __nv_bfloat16& l) {
    h = __float2bfloat16(v);
    l = __float2bfloat16(v - __bfloat162float(h));
}
__device__ __forceinline__ float tobf(float x) {
    return __bfloat162float(__float2bfloat16(x));
}
// pack two floats as bf16x2: first arg -> LOW half
__device__ __forceinline__ uint32_t packbf(float lo_, float hi_) {
    uint32_t r;
    asm("cvt.rn.bf16x2.f32 %0, %1, %2;" : "=r"(r) : "f"(hi_), "f"(lo_));
    return r;
}

// swizzled smem offset for tiles with 64B rows (4 x 16B chunks per row)
__device__ __forceinline__ uint32_t swz(uint32_t row, uint32_t c) {
    return row * 64u + ((c ^ ((row >> 1) & 3u)) << 4);
}
__device__ __forceinline__ void cp16(uint32_t sm, const void* gm) {
    asm volatile("cp.async.cg.shared.global [%0], [%1], 16;" :: "r"(sm), "l"(gm));
}
#define CP_COMMIT() asm volatile("cp.async.commit_group;" ::: "memory")
#define ZERO16(addr) asm volatile("st.shared.v4.b32 [%0], {%1,%1,%1,%1};" :: "r"(addr), "r"(0u) : "memory")

#define LDMX4(r0, r1, r2, r3, addr) \
    asm volatile("ldmatrix.sync.aligned.m8n8.x4.shared.b16 {%0,%1,%2,%3}, [%4];" \
        : "=r"(r0), "=r"(r1), "=r"(r2), "=r"(r3) : "r"(addr))
#define LDMX2(r0, r1, addr) \
    asm volatile("ldmatrix.sync.aligned.m8n8.x2.shared.b16 {%0,%1}, [%2];" \
        : "=r"(r0), "=r"(r1) : "r"(addr))
#define LDMX2T(r0, r1, addr) \
    asm volatile("ldmatrix.sync.aligned.m8n8.x2.trans.shared.b16 {%0,%1}, [%2];" \
        : "=r"(r0), "=r"(r1) : "r"(addr))

#define MMA16816(d, a, b) \
    asm volatile("mma.sync.aligned.m16n8k16.row.col.f32.bf16.bf16.f32 " \
        "{%0,%1,%2,%3}, {%4,%5,%6,%7}, {%8,%9}, {%0,%1,%2,%3};" \
        : "+f"((d)[0]), "+f"((d)[1]), "+f"((d)[2]), "+f"((d)[3]) \
        : "r"((a)[0]), "r"((a)[1]), "r"((a)[2]), "r"((a)[3]), \
          "r"((b)[0]), "r"((b)[1]))

// ---------------- kernel 1: x = skip + x_up ; LN1(skip)->SKh/l ; LN1(x_up)->Qh/l ----------------
__global__ void add_ln1_kernel(const float* __restrict__ skip,
                               const float* __restrict__ xup,
                               const float* __restrict__ g,
                               const float* __restrict__ b)
{
    int l = blockIdx.x, tid = threadIdx.x;
    const float* srow = skip + (size_t)l * C_DIM;
    const float* urow = xup  + (size_t)l * C_DIM;
    float sv[3], uv[3];
    float ssum = 0.f, ssq = 0.f, usum = 0.f, usq = 0.f;
#pragma unroll
    for (int t = 0; t < 3; t++) {
        int c = tid + t * 128;
        float s = srow[c], u = urow[c];
        sv[t] = s; uv[t] = u;
        g_X[(size_t)l * C_DIM + c] = s + u;
        ssum += s; ssq += s * s; usum += u; usq += u * u;
    }
    __shared__ float red[4][4];
#pragma unroll
    for (int o = 16; o > 0; o >>= 1) {
        ssum += __shfl_down_sync(0xffffffffu, ssum, o);
        ssq  += __shfl_down_sync(0xffffffffu, ssq , o);
        usum += __shfl_down_sync(0xffffffffu, usum, o);
        usq  += __shfl_down_sync(0xffffffffu, usq , o);
    }
    int warp = tid >> 5, lane = tid & 31;
    if (lane == 0) { red[warp][0]=ssum; red[warp][1]=ssq; red[warp][2]=usum; red[warp][3]=usq; }
    __syncthreads();
    float S  = red[0][0]+red[1][0]+red[2][0]+red[3][0];
    float SQ = red[0][1]+red[1][1]+red[2][1]+red[3][1];
    float U  = red[0][2]+red[1][2]+red[2][2]+red[3][2];
    float UQ = red[0][3]+red[1][3]+red[2][3]+red[3][3];
    const float inv = 1.f / (float)C_DIM;
    float ms = S * inv, vs = SQ * inv - ms * ms;
    float mu = U * inv, vu = UQ * inv - mu * mu;
    float rs = rsqrtf(vs + 1e-5f), ru = rsqrtf(vu + 1e-5f);

    int d = l / 784, rem = l % 784, hh = rem / 28, ww = rem % 28;
    int widx = ((d / 7) * 4 + hh / 7) * 4 + ww / 7;
    int nidx = ((d % 7) * 7 + hh % 7) * 7 + ww % 7;
    size_t wrow = (size_t)(widx * NTOK + nidx) * C_DIM;
#pragma unroll
    for (int t = 0; t < 3; t++) {
        int c = tid + t * 128;
        float gg = g[c], bb = b[c];
        float skv = (sv[t] - ms) * rs * gg + bb;
        __nv_bfloat16 h, lo; bsplit(skv, h, lo);
        g_SKh[wrow + c] = h; g_SKl[wrow + c] = lo;
        float qv = (uv[t] - mu) * ru * gg + bb;
        __nv_bfloat16 qh, ql; bsplit(qv, qh, ql);
        g_Qh[wrow + c] = qh; g_Ql[wrow + c] = ql;
    }
}

// ---------------- kernel 2: expand relative position bias (stride 344) ----------------
__global__ void bias_kernel(const float* __restrict__ rpb)
{
    int i = blockIdx.x * blockDim.x + threadIdx.x;
    if (i >= NHEAD * NTOK * NTOK) return;
    int h = i / (NTOK * NTOK);
    int r = i % (NTOK * NTOK);
    int q = r / NTOK, k = r % NTOK;
    int z1 = q / 49, y1 = (q / 7) % 7, x1 = q % 7;
    int z2 = k / 49, y2 = (k / 7) % 7, x2 = k % 7;
    int rel = (z1 - z2 + 6) * 169 + (y1 - y2 + 6) * 13 + (x1 - x2 + 6);
    g_bias[((size_t)h * NTOK + q) * BSTR + k] = rpb[rel * NHEAD + h];
}

// ---------------- weight prep: W[K][N] fp32 -> Wt_hi/lo [N][K] bf16 ----------------
__global__ void wprep_kernel(const float* __restrict__ W,
                             __nv_bfloat16* __restrict__ Th,
                             __nv_bfloat16* __restrict__ Tl, int K, int N)
{
    int i = blockIdx.x * blockDim.x + threadIdx.x;
    if (i >= K * N) return;
    int n = i / K, k = i % K;
    float w = W[(size_t)k * N + n];
    __nv_bfloat16 h, lo; bsplit(w, h, lo);
    Th[i] = h; Tl[i] = lo;
}

// ---------------- mma.sync GEMM: C[M,N] = A @ Bt^T  (Bt is [N][K]) ----------------
// EPI 0: bf16 split store (KV)   1: proj scatter-add residual into g_X (window reverse)
// EPI 2: gelu -> bf16 hi/lo      3: out = Xres + v (bounded)
#define GBM 128
#define GBN 128
#define GBK 32
#define STAGE 32768

template <int EPI>
__global__ void __launch_bounds__(256)
hmma_gemm(const __nv_bfloat16* __restrict__ Ah, const __nv_bfloat16* __restrict__ Al,
          const __nv_bfloat16* __restrict__ Bh, const __nv_bfloat16* __restrict__ Bl,
          const float* __restrict__ bias, float* __restrict__ Cf,
          __nv_bfloat16* __restrict__ Ch, __nv_bfloat16* __restrict__ Cl,
          const float* __restrict__ Xres, int K, int N, int Mvalid)
{
    extern __shared__ char smem[];
    const int tid = threadIdx.x, lane = tid & 31, wid = tid >> 5;
    const int rowBase = blockIdx.y * GBM, colBase = blockIdx.x * GBN;
    const int wM = (wid & 3) * 32, wN = (wid >> 2) * 64;
    const uint32_t sbase = smem_u32(smem);

    float acc[2][8][4];
#pragma unroll
    for (int m = 0; m < 2; m++)
#pragma unroll
        for (int n = 0; n < 8; n++)
#pragma unroll
            for (int v = 0; v < 4; v++) acc[m][n][v] = 0.f;

    const int NC = K / GBK;

    auto issue = [&](int ch) {
        uint32_t sb = sbase + (ch & 1) * STAGE;
        int k0 = ch * GBK;
#pragma unroll
        for (int i = 0; i < 2; i++) {
            int ci = tid + i * 256;
            int r = ci >> 2, c = ci & 3;
            uint32_t so = swz(r, c);
            size_t aoff = (size_t)(rowBase + r) * K + k0 + c * 8;
            size_t boff = (size_t)(colBase + r) * K + k0 + c * 8;
            cp16(sb +         so, Ah + aoff);
            cp16(sb +  8192 + so, Al + aoff);
            cp16(sb + 16384 + so, Bh + boff);
            cp16(sb + 24576 + so, Bl + boff);
        }
        CP_COMMIT();
    };

    issue(0);
    for (int ch = 0; ch < NC; ch++) {
        if (ch + 1 < NC) {
            issue(ch + 1);
            asm volatile("cp.async.wait_group 1;" ::: "memory");
        } else {
            asm volatile("cp.async.wait_group 0;" ::: "memory");
        }
        __syncthreads();
        uint32_t sb = sbase + (ch & 1) * STAGE;

#pragma unroll
        for (int ks = 0; ks < 2; ks++) {
            uint32_t aH[2][4], aL[2][4];
#pragma unroll
            for (int m = 0; m < 2; m++) {
                uint32_t row = wM + m * 16 + (lane & 15);
                uint32_t c = ks * 2 + (lane >> 4);
                uint32_t ad = sb + swz(row, c);
                LDMX4(aH[m][0], aH[m][1], aH[m][2], aH[m][3], ad);
                LDMX4(aL[m][0], aL[m][1], aL[m][2], aL[m][3], ad + 8192);
            }
            uint32_t bH[8][2], bL[8][2];
#pragma unroll
            for (int nb = 0; nb < 4; nb++) {
                uint32_t row = wN + nb * 16 + (lane & 7) + ((lane >> 4) & 1) * 8;
                uint32_t c = ks * 2 + ((lane >> 3) & 1);
                uint32_t bd = sb + 16384 + swz(row, c);
                LDMX4(bH[nb*2][0], bH[nb*2][1], bH[nb*2+1][0], bH[nb*2+1][1], bd);
                LDMX4(bL[nb*2][0], bL[nb*2][1], bL[nb*2+1][0], bL[nb*2+1][1], bd + 8192);
            }
#pragma unroll
            for (int m = 0; m < 2; m++)
#pragma unroll
                for (int n = 0; n < 8; n++) {
                    MMA16816(acc[m][n], aH[m], bH[n]);
                    MMA16816(acc[m][n], aH[m], bL[n]);
                    MMA16816(acc[m][n], aL[m], bH[n]);
                }
        }
        __syncthreads();
    }

    const int gid = lane >> 2, tig = lane & 3;
#pragma unroll
    for (int m = 0; m < 2; m++) {
#pragma unroll
        for (int rr = 0; rr < 2; rr++) {
            int row = rowBase + wM + m * 16 + gid + rr * 8;
            if (EPI == 0) {
#pragma unroll
                for (int n = 0; n < 8; n++) {
                    int col = colBase + wN + n * 8 + tig * 2;
#pragma unroll
                    for (int j = 0; j < 2; j++) {
                        float v = acc[m][n][rr * 2 + j] + bias[col + j];
                        __nv_bfloat16 h, lo; bsplit(v, h, lo);
                        Ch[(size_t)row * N + col + j] = h;
                        Cl[(size_t)row * N + col + j] = lo;
                    }
                }
            } else if (EPI == 1) {
                if (row < Mvalid) {
                    int widx = row / NTOK, nn = row % NTOK;
                    int dd =  (widx >> 4)      * 7 + nn / 49;
                    int hh = ((widx >> 2) & 3) * 7 + (nn / 7) % 7;
                    int ww =  (widx & 3)       * 7 + nn % 7;
                    int lrow = (dd * 28 + hh) * 28 + ww;
#pragma unroll
                    for (int n = 0; n < 8; n++) {
                        int col = colBase + wN + n * 8 + tig * 2;
                        float* p = Cf + (size_t)lrow * N + col;
                        p[0] += acc[m][n][rr * 2 + 0] + bias[col];
                        p[1] += acc[m][n][rr * 2 + 1] + bias[col + 1];
                    }
                }
            } else if (EPI == 2) {
#pragma unroll
                for (int n = 0; n < 8; n++) {
                    int col = colBase + wN + n * 8 + tig * 2;
#pragma unroll
                    for (int j = 0; j < 2; j++) {
                        float v = acc[m][n][rr * 2 + j] + bias[col + j];
                        float t = tanhf(0.7978845608028654f * (v + 0.044715f * v * v * v));
                        float gv = 0.5f * v * (1.f + t);
                        __nv_bfloat16 h, lo; bsplit(gv, h, lo);
                        Ch[(size_t)row * N + col + j] = h;
                        Cl[(size_t)row * N + col + j] = lo;
                    }
                }
            } else {
                if (row < Mvalid) {
#pragma unroll
                    for (int n = 0; n < 8; n++) {
                        int col = colBase + wN + n * 8 + tig * 2;
                        const float* xr = Xres + (size_t)row * N + col;
                        float2 v;
                        v.x = xr[0] + acc[m][n][rr * 2 + 0] + bias[col];
                        v.y = xr[1] + acc[m][n][rr * 2 + 1] + bias[col + 1];
                        *(float2*)(Cf + (size_t)row * N + col) = v;
                    }
                }
            }
        }
    }
}

// ---------------- flash attention, mma.sync, per (window, head) ----------------
// smem: Kh[384x32] Kl[384x32] Vh[384x32] (24576B each) + Qh/Ql[128x32] (8192B each)
#define ASM_KH 0
#define ASM_KL 24576
#define ASM_VH 49152
#define ASM_QH 73728
#define ASM_QL 81920
#define ATT_SMEM 90112

__global__ void __launch_bounds__(256)
attn_mma_kernel()
{
    extern __shared__ char sm[];
    const uint32_t sb = smem_u32(sm);
    const int w = blockIdx.x / NHEAD;
    const int h = blockIdx.x % NHEAD;
    const int tid = threadIdx.x, lane = tid & 31, wid = tid >> 5;
    const int gid = lane >> 2, tig = lane & 3;

    // zero K/V region (covers pad rows 343..383)
    uint4 z4 = make_uint4(0, 0, 0, 0);
    for (int i = tid; i < 73728 / 16; i += 256)
        reinterpret_cast<uint4*>(sm)[i] = z4;
    __syncthreads();

    // stage K (hi+lo) and V (hi) for this (window, head)
    {
        const __nv_bfloat16* kh = g_KVh + (size_t)(w * NTOK) * C2 + h * HD;
        const __nv_bfloat16* kl = g_KVl + (size_t)(w * NTOK) * C2 + h * HD;
        const __nv_bfloat16* vh = kh + C_DIM;
        for (int i = tid; i < NTOK * 4; i += 256) {
            int row = i >> 2, c = i & 3;
            uint32_t so = swz(row, c);
            size_t go = (size_t)row * C2 + c * 8;
            cp16(sb + ASM_KH + so, kh + go);
            cp16(sb + ASM_KL + so, kl + go);
            cp16(sb + ASM_VH + so, vh + go);
        }
        CP_COMMIT();
    }
    asm volatile("cp.async.wait_group 0;" ::: "memory");
    __syncthreads();

    const float scale = 0.17677669529663687f; // 1/sqrt(32)
    const float* bb = g_bias + (size_t)h * NTOK * BSTR;

    for (int qs = 0; qs < 3; qs++) {
        int q0 = qs * 128;
        // stage Q supertile (128 rows)
        {
            const __nv_bfloat16* qh = g_Qh + ((size_t)(w * NTOK + q0)) * C_DIM + h * HD;
            const __nv_bfloat16* ql = g_Ql + ((size_t)(w * NTOK + q0)) * C_DIM + h * HD;
            for (int i = tid; i < 512; i += 256) {
                int row = i >> 2, c = i & 3;
                uint32_t soh = sb + ASM_QH + swz(row, c);
                uint32_t sol = sb + ASM_QL + swz(row, c);
                if (q0 + row < NTOK) {
                    size_t go = (size_t)row * C_DIM + c * 8;
                    cp16(soh, qh + go);
                    cp16(sol, ql + go);
                } else {
                    ZERO16(soh);
                    ZERO16(sol);
                }
            }
            CP_COMMIT();
        }
        asm volatile("cp.async.wait_group 0;" ::: "memory");
        __syncthreads();

        // Q fragments (warp owns 16 rows)
        uint32_t qfh[2][4], qfl[2][4];
#pragma unroll
        for (int ks = 0; ks < 2; ks++) {
            uint32_t row = wid * 16 + (lane & 15);
            uint32_t c = 2 * ks + (lane >> 4);
            uint32_t ah = sb + ASM_QH + swz(row, c);
            uint32_t al = sb + ASM_QL + swz(row, c);
            LDMX4(qfh[ks][0], qfh[ks][1], qfh[ks][2], qfh[ks][3], ah);
            LDMX4(qfl[ks][0], qfl[ks][1], qfl[ks][2], qfl[ks][3], al);
        }
        __syncthreads();   // all warps done reading Q smem before next restage

        int qrow0 = q0 + wid * 16 + gid;
        int qrow1 = qrow0 + 8;
        bool rv0 = qrow0 < NTOK, rv1 = qrow1 < NTOK;
        float m0 = -1e30f, m1 = -1e30f, l0 = 0.f, l1 = 0.f;
        float oacc[4][4];
#pragma unroll
        for (int o = 0; o < 4; o++)
#pragma unroll
            for (int v = 0; v < 4; v++) oacc[o][v] = 0.f;

        for (int kt = 0; kt < 6; kt++) {
            int t0 = kt * 64;
            float sacc[8][4];
#pragma unroll
            for (int n = 0; n < 8; n++)
#pragma unroll
                for (int v = 0; v < 4; v++) sacc[n][v] = 0.f;

            // S = Q K^T (3-product split)
#pragma unroll
            for (int ks = 0; ks < 2; ks++) {
                uint32_t krow = t0 + (lane & 7);
                uint32_t kc = 2 * ks + ((lane >> 3) & 1);
#pragma unroll
                for (int nb = 0; nb < 8; nb++) {
                    uint32_t ad = swz(krow + nb * 8, kc);
                    uint32_t kh[2], kl[2];
                    LDMX2(kh[0], kh[1], sb + ASM_KH + ad);
                    LDMX2(kl[0], kl[1], sb + ASM_KL + ad);
                    MMA16816(sacc[nb], qfh[ks], kh);
                    MMA16816(sacc[nb], qfh[ks], kl);
                    MMA16816(sacc[nb], qfl[ks], kh);
                }
            }

            // scale + bias + mask, row max
            float rmax0 = -1e30f, rmax1 = -1e30f;
#pragma unroll
            for (int nb = 0; nb < 8; nb++) {
                int col = t0 + nb * 8 + tig * 2;
                if (col < NTOK) {
                    bool c1 = (col + 1 < NTOK);
                    float2 b0 = rv0 ? *(const float2*)(bb + (size_t)qrow0 * BSTR + col)
                                    : make_float2(0.f, 0.f);
                    float2 b1 = rv1 ? *(const float2*)(bb + (size_t)qrow1 * BSTR + col)
                                    : make_float2(0.f, 0.f);
                    sacc[nb][0] = sacc[nb][0] * scale + b0.x;
                    sacc[nb][1] = c1 ? sacc[nb][1] * scale + b0.y : -1e30f;
                    sacc[nb][2] = sacc[nb][2] * scale + b1.x;
                    sacc[nb][3] = c1 ? sacc[nb][3] * scale + b1.y : -1e30f;
                } else {
                    sacc[nb][0] = sacc[nb][1] = sacc[nb][2] = sacc[nb][3] = -1e30f;
                }
                rmax0 = fmaxf(rmax0, fmaxf(sacc[nb][0], sacc[nb][1]));
                rmax1 = fmaxf(rmax1, fmaxf(sacc[nb][2], sacc[nb][3]));
            }
            rmax0 = fmaxf(rmax0, __shfl_xor_sync(0xffffffffu, rmax0, 1));
            rmax0 = fmaxf(rmax0, __shfl_xor_sync(0xffffffffu, rmax0, 2));
            rmax1 = fmaxf(rmax1, __shfl_xor_sync(0xffffffffu, rmax1, 1));
            rmax1 = fmaxf(rmax1, __shfl_xor_sync(0xffffffffu, rmax1, 2));

            float mn0 = fmaxf(m0, rmax0), mn1 = fmaxf(m1, rmax1);
            float sc0 = __expf(m0 - mn0), sc1 = __expf(m1 - mn1);
            m0 = mn0; m1 = mn1;

            float rs0 = 0.f, rs1 = 0.f;
#pragma unroll
            for (int nb = 0; nb < 8; nb++) {
                sacc[nb][0] = __expf(sacc[nb][0] - m0);
                sacc[nb][1] = __expf(sacc[nb][1] - m0);
                sacc[nb][2] = __expf(sacc[nb][2] - m1);
                sacc[nb][3] = __expf(sacc[nb][3] - m1);
                rs0 += sacc[nb][0] + sacc[nb][1];
                rs1 += sacc[nb][2] + sacc[nb][3];
            }
            rs0 += __shfl_xor_sync(0xffffffffu, rs0, 1);
            rs0 += __shfl_xor_sync(0xffffffffu, rs0, 2);
            rs1 += __shfl_xor_sync(0xffffffffu, rs1, 1);
            rs1 += __shfl_xor_sync(0xffffffffu, rs1, 2);
            l0 = l0 * sc0 + rs0;
            l1 = l1 * sc1 + rs1;
#pragma unroll
            for (int o = 0; o < 4; o++) {
                oacc[o][0] *= sc0; oacc[o][1] *= sc0;
                oacc[o][2] *= sc1; oacc[o][3] *= sc1;
            }

            // O += P V  (P split hi/lo, V hi only)
#pragma unroll
            for (int ks2 = 0; ks2 < 4; ks2++) {
                float* f0 = sacc[2 * ks2];
                float* f1 = sacc[2 * ks2 + 1];
                float h00 = tobf(f0[0]), h01 = tobf(f0[1]), h02 = tobf(f0[2]), h03 = tobf(f0[3]);
                float h10 = tobf(f1[0]), h11 = tobf(f1[1]), h12 = tobf(f1[2]), h13 = tobf(f1[3]);
                uint32_t pah[4], pal[4];
                pah[0] = packbf(h00, h01);
                pah[1] = packbf(h02, h03);
                pah[2] = packbf(h10, h11);
                pah[3] = packbf(h12, h13);
                pal[0] = packbf(f0[0] - h00, f0[1] - h01);
                pal[1] = packbf(f0[2] - h02, f0[3] - h03);
                pal[2] = packbf(f1[0] - h10, f1[1] - h11);
                pal[3] = packbf(f1[2] - h12, f1[3] - h13);
                uint32_t vrow = t0 + ks2 * 16 + (lane & 15);
#pragma unroll
                for (int onb = 0; onb < 4; onb++) {
                    uint32_t bv[2];
                    LDMX2T(bv[0], bv[1], sb + ASM_VH + swz(vrow, onb));
                    MMA16816(oacc[onb], pah, bv);
                    MMA16816(oacc[onb], pal, bv);
                }
            }
        } // kt

        float inv0 = 1.f / l0, inv1 = 1.f / l1;
#pragma unroll
        for (int onb = 0; onb < 4; onb++) {
            int ch = h * HD + onb * 8 + tig * 2;
            if (rv0) {
                float x = oacc[onb][0] * inv0, y = oacc[onb][1] * inv0;
                float hx = tobf(x), hy = tobf(y);
                size_t base = ((size_t)(w * NTOK + qrow0)) * C_DIM + ch;
                *(uint32_t*)(g_Oh + base) = packbf(hx, hy);
                *(uint32_t*)(g_Ol + base) = packbf(x - hx, y - hy);
            }
            if (rv1) {
                float x = oacc[onb][2] * inv1, y = oacc[onb][3] * inv1;
                float hx = tobf(x), hy = tobf(y);
                size_t base = ((size_t)(w * NTOK + qrow1)) * C_DIM + ch;
                *(uint32_t*)(g_Oh + base) = packbf(hx, hy);
                *(uint32_t*)(g_Ol + base) = packbf(x - hx, y - hy);
            }
        }
    } // qs
}

// ---------------- LN2 -> Yh/Yl ----------------
__global__ void ln2_kernel(const float* __restrict__ g, const float* __restrict__ b)
{
    int l = blockIdx.x, tid = threadIdx.x;
    const float* row = g_X + (size_t)l * C_DIM;
    float xv[3];
    float s = 0.f, sq = 0.f;
#pragma unroll
    for (int t = 0; t < 3; t++) {
        int c = tid + t * 128;
        float x = row[c];
        xv[t] = x; s += x; sq += x * x;
    }
    __shared__ float red[4][2];
#pragma unroll
    for (int o = 16; o > 0; o >>= 1) {
        s  += __shfl_down_sync(0xffffffffu, s , o);
        sq += __shfl_down_sync(0xffffffffu, sq, o);
    }
    int warp = tid >> 5, lane = tid & 31;
    if (lane == 0) { red[warp][0] = s; red[warp][1] = sq; }
    __syncthreads();
    float S  = red[0][0]+red[1][0]+red[2][0]+red[3][0];
    float SQ = red[0][1]+red[1][1]+red[2][1]+red[3][1];
    const float inv = 1.f / (float)C_DIM;
    float m = S * inv;
    float rs = rsqrtf(SQ * inv - m * m + 1e-5f);
#pragma unroll
    for (int t = 0; t < 3; t++) {
        int c = tid + t * 128;
        float y = (xv[t] - m) * rs * g[c] + b[c];
        __nv_bfloat16 h, lo; bsplit(y, h, lo);
        g_Yh[(size_t)l * C_DIM + c] = h;
        g_Yl[(size_t)l * C_DIM + c] = lo;
    }
}

// ---------------- launch ----------------
extern "C" void kernel_launch(void* const* d_in, const int* in_sizes, int n_in,
                              void* d_out, int out_size)
{
    const float* skip = (const float*)d_in[0];
    const float* x_up = (const float*)d_in[1];
    int o = (n_in >= 18) ? 5 : 2;
    const float* ln1_g  = (const float*)d_in[o + 0];
    const float* ln1_b  = (const float*)d_in[o + 1];
    const float* kv_w   = (const float*)d_in[o + 2];
    const float* kv_b   = (const float*)d_in[o + 3];
    const float* rpb    = (const float*)d_in[o + 4];
    const float* proj_w = (const float*)d_in[o + 5];
    const float* proj_b = (const float*)d_in[o + 6];
    const float* ln2_g  = (const float*)d_in[o + 7];
    const float* ln2_b  = (const float*)d_in[o + 8];
    const float* mlp_w1 = (const float*)d_in[o + 9];
    const float* mlp_b1 = (const float*)d_in[o + 10];
    const float* mlp_w2 = (const float*)d_in[o + 11];
    const float* mlp_b2 = (const float*)d_in[o + 12];
    float* out = (float*)d_out;

    float* pX;
    __nv_bfloat16 *pSKh, *pSKl, *pKVh, *pKVl, *pOh, *pOl, *pYh, *pYl, *pH1h, *pH1l;
    __nv_bfloat16 *pWkvh, *pWkvl, *pWprh, *pWprl, *pW1h, *pW1l, *pW2h, *pW2l;
    cudaGetSymbolAddress((void**)&pX,   g_X);
    cudaGetSymbolAddress((void**)&pSKh, g_SKh); cudaGetSymbolAddress((void**)&pSKl, g_SKl);
    cudaGetSymbolAddress((void**)&pKVh, g_KVh); cudaGetSymbolAddress((void**)&pKVl, g_KVl);
    cudaGetSymbolAddress((void**)&pOh,  g_Oh);  cudaGetSymbolAddress((void**)&pOl,  g_Ol);
    cudaGetSymbolAddress((void**)&pYh,  g_Yh);  cudaGetSymbolAddress((void**)&pYl,  g_Yl);
    cudaGetSymbolAddress((void**)&pH1h, g_H1h); cudaGetSymbolAddress((void**)&pH1l, g_H1l);
    cudaGetSymbolAddress((void**)&pWkvh, g_Wkvh); cudaGetSymbolAddress((void**)&pWkvl, g_Wkvl);
    cudaGetSymbolAddress((void**)&pWprh, g_Wprh); cudaGetSymbolAddress((void**)&pWprl, g_Wprl);
    cudaGetSymbolAddress((void**)&pW1h,  g_W1h);  cudaGetSymbolAddress((void**)&pW1l,  g_W1l);
    cudaGetSymbolAddress((void**)&pW2h,  g_W2h);  cudaGetSymbolAddress((void**)&pW2l,  g_W2l);

    int gemm_smem = 2 * STAGE;  // 64 KB
    cudaFuncSetAttribute(hmma_gemm<0>, cudaFuncAttributeMaxDynamicSharedMemorySize, gemm_smem);
    cudaFuncSetAttribute(hmma_gemm<1>, cudaFuncAttributeMaxDynamicSharedMemorySize, gemm_smem);
    cudaFuncSetAttribute(hmma_gemm<2>, cudaFuncAttributeMaxDynamicSharedMemorySize, gemm_smem);
    cudaFuncSetAttribute(hmma_gemm<3>, cudaFuncAttributeMaxDynamicSharedMemorySize, gemm_smem);
    cudaFuncSetAttribute(attn_mma_kernel, cudaFuncAttributeMaxDynamicSharedMemorySize, ATT_SMEM);

    const int MT = MPAD / GBM;  // 172

    // launch order arranged so launch index 5 (ncu -s 5 -c 1) = attention kernel
    add_ln1_kernel<<<L_TOK, 128>>>(skip, x_up, ln1_g, ln1_b);                       // 0
    bias_kernel<<<(NHEAD * NTOK * NTOK + 255) / 256, 256>>>(rpb);                   // 1
    wprep_kernel<<<(C_DIM * C2 + 255) / 256, 256>>>(kv_w, pWkvh, pWkvl, C_DIM, C2); // 2
    hmma_gemm<0><<<dim3(C2 / GBN, MT), 256, gemm_smem>>>(pSKh, pSKl, pWkvh, pWkvl,  // 3
        kv_b, nullptr, pKVh, pKVl, nullptr, C_DIM, C2, L_TOK);
    wprep_kernel<<<(C_DIM * C_DIM + 255) / 256, 256>>>(proj_w, pWprh, pWprl, C_DIM, C_DIM); // 4
    attn_mma_kernel<<<NWIN * NHEAD, 256, ATT_SMEM>>>();                             // 5 <- profiled
    hmma_gemm<1><<<dim3(C_DIM / GBN, MT), 256, gemm_smem>>>(pOh, pOl, pWprh, pWprl, // 6
        proj_b, pX, nullptr, nullptr, nullptr, C_DIM, C_DIM, L_TOK);
    ln2_kernel<<<L_TOK, 128>>>(ln2_g, ln2_b);                                       // 7
    wprep_kernel<<<(C_DIM * C4 + 255) / 256, 256>>>(mlp_w1, pW1h, pW1l, C_DIM, C4); // 8
    hmma_gemm<2><<<dim3(C4 / GBN, MT), 256, gemm_smem>>>(pYh, pYl, pW1h, pW1l,      // 9
        mlp_b1, nullptr, pH1h, pH1l, nullptr, C_DIM, C4, L_TOK);
    wprep_kernel<<<(C4 * C_DIM + 255) / 256, 256>>>(mlp_w2, pW2h, pW2l, C4, C_DIM); // 10
    hmma_gemm<3><<<dim3(C_DIM / GBN, MT), 256, gemm_smem>>>(pH1h, pH1l, pW2h, pW2l, // 11
        mlp_b2, out, nullptr, nullptr, pX, C4, C_DIM, L_TOK);
}

// round 7
// speedup vs baseline: 2.8685x; 1.1093x over previous
#include <cuda_runtime.h>
#include <cuda_bf16.h>
#include <math.h>
#include <stdint.h>

#define L_TOK 21952
#define MPAD  22016
#define C_DIM 384
#define C2    768
#define C4    1536
#define NHEAD 12
#define HD    32
#define NWIN  64
#define NTOK  343
#define BSTR  344   // padded bias row stride

// ---------------- scratch (device globals) ----------------
__device__ float g_X [(size_t)L_TOK * C_DIM];
__device__ __nv_bfloat16 g_Qh [(size_t)L_TOK * C_DIM], g_Ql [(size_t)L_TOK * C_DIM];
__device__ __nv_bfloat16 g_KVh[(size_t)MPAD * C2],     g_KVl[(size_t)MPAD * C2];
__device__ __nv_bfloat16 g_SKh[(size_t)MPAD * C_DIM],  g_SKl[(size_t)MPAD * C_DIM];
__device__ __nv_bfloat16 g_Oh [(size_t)MPAD * C_DIM],  g_Ol [(size_t)MPAD * C_DIM];
__device__ __nv_bfloat16 g_Yh [(size_t)MPAD * C_DIM],  g_Yl [(size_t)MPAD * C_DIM];
__device__ __nv_bfloat16 g_H1h[(size_t)MPAD * C4],     g_H1l[(size_t)MPAD * C4];
__device__ float g_bias[NHEAD * NTOK * BSTR];
// weights transposed to [N][K] row-major, split hi/lo
__device__ __nv_bfloat16 g_Wkvh[C2 * C_DIM],    g_Wkvl[C2 * C_DIM];
__device__ __nv_bfloat16 g_Wprh[C_DIM * C_DIM], g_Wprl[C_DIM * C_DIM];
__device__ __nv_bfloat16 g_W1h [C4 * C_DIM],    g_W1l [C4 * C_DIM];
__device__ __nv_bfloat16 g_W2h [C_DIM * C4],    g_W2l [C_DIM * C4];

// ---------------- helpers ----------------
__device__ __forceinline__ uint32_t smem_u32(const void* p) {
    uint32_t a;
    asm("{ .reg .u64 t; cvta.to.shared.u64 t, %1; cvt.u32.u64 %0, t; }" : "=r"(a) : "l"(p));
    return a;
}
__device__ __forceinline__ void bsplit(float v, __nv_bfloat16& h, __nv_bfloat16& l) {
    h = __float2bfloat16(v);
    l = __float2bfloat16(v - __bfloat162float(h));
}
__device__ __forceinline__ float tobf(float x) {
    return __bfloat162float(__float2bfloat16(x));
}
// pack two floats as bf16x2: first arg -> LOW half
__device__ __forceinline__ uint32_t packbf(float lo_, float hi_) {
    uint32_t r;
    asm("cvt.rn.bf16x2.f32 %0, %1, %2;" : "=r"(r) : "f"(hi_), "f"(lo_));
    return r;
}

// swizzled smem offset for tiles with 64B rows (4 x 16B chunks per row)
__device__ __forceinline__ uint32_t swz(uint32_t row, uint32_t c) {
    return row * 64u + ((c ^ ((row >> 1) & 3u)) << 4);
}
__device__ __forceinline__ void cp16(uint32_t sm, const void* gm) {
    asm volatile("cp.async.cg.shared.global [%0], [%1], 16;" :: "r"(sm), "l"(gm));
}
#define CP_COMMIT() asm volatile("cp.async.commit_group;" ::: "memory")
#define ZERO16(addr) asm volatile("st.shared.v4.b32 [%0], {%1,%1,%1,%1};" :: "r"(addr), "r"(0u) : "memory")

#define LDMX4(r0, r1, r2, r3, addr) \
    asm volatile("ldmatrix.sync.aligned.m8n8.x4.shared.b16 {%0,%1,%2,%3}, [%4];" \
        : "=r"(r0), "=r"(r1), "=r"(r2), "=r"(r3) : "r"(addr))
#define LDMX2(r0, r1, addr) \
    asm volatile("ldmatrix.sync.aligned.m8n8.x2.shared.b16 {%0,%1}, [%2];" \
        : "=r"(r0), "=r"(r1) : "r"(addr))
#define LDMX2T(r0, r1, addr) \
    asm volatile("ldmatrix.sync.aligned.m8n8.x2.trans.shared.b16 {%0,%1}, [%2];" \
        : "=r"(r0), "=r"(r1) : "r"(addr))

#define MMA16816(d, a, b) \
    asm volatile("mma.sync.aligned.m16n8k16.row.col.f32.bf16.bf16.f32 " \
        "{%0,%1,%2,%3}, {%4,%5,%6,%7}, {%8,%9}, {%0,%1,%2,%3};" \
        : "+f"((d)[0]), "+f"((d)[1]), "+f"((d)[2]), "+f"((d)[3]) \
        : "r"((a)[0]), "r"((a)[1]), "r"((a)[2]), "r"((a)[3]), \
          "r"((b)[0]), "r"((b)[1]))

// ---------------- kernel 1: x = skip + x_up ; LN1(skip)->SKh/l ; LN1(x_up)->Qh/l ----------------
__global__ void add_ln1_kernel(const float* __restrict__ skip,
                               const float* __restrict__ xup,
                               const float* __restrict__ g,
                               const float* __restrict__ b)
{
    int l = blockIdx.x, tid = threadIdx.x;
    const float* srow = skip + (size_t)l * C_DIM;
    const float* urow = xup  + (size_t)l * C_DIM;
    float sv[3], uv[3];
    float ssum = 0.f, ssq = 0.f, usum = 0.f, usq = 0.f;
#pragma unroll
    for (int t = 0; t < 3; t++) {
        int c = tid + t * 128;
        float s = srow[c], u = urow[c];
        sv[t] = s; uv[t] = u;
        g_X[(size_t)l * C_DIM + c] = s + u;
        ssum += s; ssq += s * s; usum += u; usq += u * u;
    }
    __shared__ float red[4][4];
#pragma unroll
    for (int o = 16; o > 0; o >>= 1) {
        ssum += __shfl_down_sync(0xffffffffu, ssum, o);
        ssq  += __shfl_down_sync(0xffffffffu, ssq , o);
        usum += __shfl_down_sync(0xffffffffu, usum, o);
        usq  += __shfl_down_sync(0xffffffffu, usq , o);
    }
    int warp = tid >> 5, lane = tid & 31;
    if (lane == 0) { red[warp][0]=ssum; red[warp][1]=ssq; red[warp][2]=usum; red[warp][3]=usq; }
    __syncthreads();
    float S  = red[0][0]+red[1][0]+red[2][0]+red[3][0];
    float SQ = red[0][1]+red[1][1]+red[2][1]+red[3][1];
    float U  = red[0][2]+red[1][2]+red[2][2]+red[3][2];
    float UQ = red[0][3]+red[1][3]+red[2][3]+red[3][3];
    const float inv = 1.f / (float)C_DIM;
    float ms = S * inv, vs = SQ * inv - ms * ms;
    float mu = U * inv, vu = UQ * inv - mu * mu;
    float rs = rsqrtf(vs + 1e-5f), ru = rsqrtf(vu + 1e-5f);

    int d = l / 784, rem = l % 784, hh = rem / 28, ww = rem % 28;
    int widx = ((d / 7) * 4 + hh / 7) * 4 + ww / 7;
    int nidx = ((d % 7) * 7 + hh % 7) * 7 + ww % 7;
    size_t wrow = (size_t)(widx * NTOK + nidx) * C_DIM;
#pragma unroll
    for (int t = 0; t < 3; t++) {
        int c = tid + t * 128;
        float gg = g[c], bb = b[c];
        float skv = (sv[t] - ms) * rs * gg + bb;
        __nv_bfloat16 h, lo; bsplit(skv, h, lo);
        g_SKh[wrow + c] = h; g_SKl[wrow + c] = lo;
        float qv = (uv[t] - mu) * ru * gg + bb;
        __nv_bfloat16 qh, ql; bsplit(qv, qh, ql);
        g_Qh[wrow + c] = qh; g_Ql[wrow + c] = ql;
    }
}

// ---------------- kernel 2: expand relative position bias (stride 344) ----------------
__global__ void bias_kernel(const float* __restrict__ rpb)
{
    int i = blockIdx.x * blockDim.x + threadIdx.x;
    if (i >= NHEAD * NTOK * NTOK) return;
    int h = i / (NTOK * NTOK);
    int r = i % (NTOK * NTOK);
    int q = r / NTOK, k = r % NTOK;
    int z1 = q / 49, y1 = (q / 7) % 7, x1 = q % 7;
    int z2 = k / 49, y2 = (k / 7) % 7, x2 = k % 7;
    int rel = (z1 - z2 + 6) * 169 + (y1 - y2 + 6) * 13 + (x1 - x2 + 6);
    g_bias[((size_t)h * NTOK + q) * BSTR + k] = rpb[rel * NHEAD + h];
}

// ---------------- weight prep: W[K][N] fp32 -> Wt_hi/lo [N][K] bf16 ----------------
__global__ void wprep_kernel(const float* __restrict__ W,
                             __nv_bfloat16* __restrict__ Th,
                             __nv_bfloat16* __restrict__ Tl, int K, int N)
{
    int i = blockIdx.x * blockDim.x + threadIdx.x;
    if (i >= K * N) return;
    int n = i / K, k = i % K;
    float w = W[(size_t)k * N + n];
    __nv_bfloat16 h, lo; bsplit(w, h, lo);
    Th[i] = h; Tl[i] = lo;
}

// ---------------- mma.sync GEMM: C[M,N] = A @ Bt^T  (Bt is [N][K]) ----------------
// EPI 0: bf16 split store (KV)   1: proj scatter-add residual into g_X (window reverse)
// EPI 2: gelu -> bf16 hi/lo      3: out = Xres + v (bounded)
#define GBM 128
#define GBN 128
#define GBK 32
#define STAGE 32768

template <int EPI>
__global__ void __launch_bounds__(256, 2)
hmma_gemm(const __nv_bfloat16* __restrict__ Ah, const __nv_bfloat16* __restrict__ Al,
          const __nv_bfloat16* __restrict__ Bh, const __nv_bfloat16* __restrict__ Bl,
          const float* __restrict__ bias, float* __restrict__ Cf,
          __nv_bfloat16* __restrict__ Ch, __nv_bfloat16* __restrict__ Cl,
          const float* __restrict__ Xres, int K, int N, int Mvalid)
{
    extern __shared__ char smem[];
    const int tid = threadIdx.x, lane = tid & 31, wid = tid >> 5;
    const int rowBase = blockIdx.y * GBM, colBase = blockIdx.x * GBN;
    const int wM = (wid & 3) * 32, wN = (wid >> 2) * 64;
    const uint32_t sbase = smem_u32(smem);

    float acc[2][8][4];
#pragma unroll
    for (int m = 0; m < 2; m++)
#pragma unroll
        for (int n = 0; n < 8; n++)
#pragma unroll
            for (int v = 0; v < 4; v++) acc[m][n][v] = 0.f;

    const int NC = K / GBK;

    auto issue = [&](int ch) {
        uint32_t sb = sbase + (ch & 1) * STAGE;
        int k0 = ch * GBK;
#pragma unroll
        for (int i = 0; i < 2; i++) {
            int ci = tid + i * 256;
            int r = ci >> 2, c = ci & 3;
            uint32_t so = swz(r, c);
            size_t aoff = (size_t)(rowBase + r) * K + k0 + c * 8;
            size_t boff = (size_t)(colBase + r) * K + k0 + c * 8;
            cp16(sb +         so, Ah + aoff);
            cp16(sb +  8192 + so, Al + aoff);
            cp16(sb + 16384 + so, Bh + boff);
            cp16(sb + 24576 + so, Bl + boff);
        }
        CP_COMMIT();
    };

    issue(0);
    for (int ch = 0; ch < NC; ch++) {
        if (ch + 1 < NC) {
            issue(ch + 1);
            asm volatile("cp.async.wait_group 1;" ::: "memory");
        } else {
            asm volatile("cp.async.wait_group 0;" ::: "memory");
        }
        __syncthreads();
        uint32_t sb = sbase + (ch & 1) * STAGE;

#pragma unroll
        for (int ks = 0; ks < 2; ks++) {
            uint32_t aH[2][4], aL[2][4];
#pragma unroll
            for (int m = 0; m < 2; m++) {
                uint32_t row = wM + m * 16 + (lane & 15);
                uint32_t c = ks * 2 + (lane >> 4);
                uint32_t ad = sb + swz(row, c);
                LDMX4(aH[m][0], aH[m][1], aH[m][2], aH[m][3], ad);
                LDMX4(aL[m][0], aL[m][1], aL[m][2], aL[m][3], ad + 8192);
            }
            uint32_t bH[8][2], bL[8][2];
#pragma unroll
            for (int nb = 0; nb < 4; nb++) {
                uint32_t row = wN + nb * 16 + (lane & 7) + ((lane >> 4) & 1) * 8;
                uint32_t c = ks * 2 + ((lane >> 3) & 1);
                uint32_t bd = sb + 16384 + swz(row, c);
                LDMX4(bH[nb*2][0], bH[nb*2][1], bH[nb*2+1][0], bH[nb*2+1][1], bd);
                LDMX4(bL[nb*2][0], bL[nb*2][1], bL[nb*2+1][0], bL[nb*2+1][1], bd + 8192);
            }
            // three passes: each accumulator reused only every 16 independent MMAs
#pragma unroll
            for (int m = 0; m < 2; m++)
#pragma unroll
                for (int n = 0; n < 8; n++)
                    MMA16816(acc[m][n], aH[m], bH[n]);
#pragma unroll
            for (int m = 0; m < 2; m++)
#pragma unroll
                for (int n = 0; n < 8; n++)
                    MMA16816(acc[m][n], aH[m], bL[n]);
#pragma unroll
            for (int m = 0; m < 2; m++)
#pragma unroll
                for (int n = 0; n < 8; n++)
                    MMA16816(acc[m][n], aL[m], bH[n]);
        }
        __syncthreads();
    }

    const int gid = lane >> 2, tig = lane & 3;
#pragma unroll
    for (int m = 0; m < 2; m++) {
#pragma unroll
        for (int rr = 0; rr < 2; rr++) {
            int row = rowBase + wM + m * 16 + gid + rr * 8;
            if (EPI == 0) {
#pragma unroll
                for (int n = 0; n < 8; n++) {
                    int col = colBase + wN + n * 8 + tig * 2;
#pragma unroll
                    for (int j = 0; j < 2; j++) {
                        float v = acc[m][n][rr * 2 + j] + bias[col + j];
                        __nv_bfloat16 h, lo; bsplit(v, h, lo);
                        Ch[(size_t)row * N + col + j] = h;
                        Cl[(size_t)row * N + col + j] = lo;
                    }
                }
            } else if (EPI == 1) {
                if (row < Mvalid) {
                    int widx = row / NTOK, nn = row % NTOK;
                    int dd =  (widx >> 4)      * 7 + nn / 49;
                    int hh = ((widx >> 2) & 3) * 7 + (nn / 7) % 7;
                    int ww =  (widx & 3)       * 7 + nn % 7;
                    int lrow = (dd * 28 + hh) * 28 + ww;
#pragma unroll
                    for (int n = 0; n < 8; n++) {
                        int col = colBase + wN + n * 8 + tig * 2;
                        float* p = Cf + (size_t)lrow * N + col;
                        p[0] += acc[m][n][rr * 2 + 0] + bias[col];
                        p[1] += acc[m][n][rr * 2 + 1] + bias[col + 1];
                    }
                }
            } else if (EPI == 2) {
#pragma unroll
                for (int n = 0; n < 8; n++) {
                    int col = colBase + wN + n * 8 + tig * 2;
#pragma unroll
                    for (int j = 0; j < 2; j++) {
                        float v = acc[m][n][rr * 2 + j] + bias[col + j];
                        float t = tanhf(0.7978845608028654f * (v + 0.044715f * v * v * v));
                        float gv = 0.5f * v * (1.f + t);
                        __nv_bfloat16 h, lo; bsplit(gv, h, lo);
                        Ch[(size_t)row * N + col + j] = h;
                        Cl[(size_t)row * N + col + j] = lo;
                    }
                }
            } else {
                if (row < Mvalid) {
#pragma unroll
                    for (int n = 0; n < 8; n++) {
                        int col = colBase + wN + n * 8 + tig * 2;
                        const float* xr = Xres + (size_t)row * N + col;
                        float2 v;
                        v.x = xr[0] + acc[m][n][rr * 2 + 0] + bias[col];
                        v.y = xr[1] + acc[m][n][rr * 2 + 1] + bias[col + 1];
                        *(float2*)(Cf + (size_t)row * N + col) = v;
                    }
                }
            }
        }
    }
}

// ---------------- flash attention, mma.sync, per (window, head) ----------------
// smem: Kh[384x32] Kl[384x32] Vh[384x32] (24576B each) + Qh/Ql[128x32] (8192B each)
#define ASM_KH 0
#define ASM_KL 24576
#define ASM_VH 49152
#define ASM_QH 73728
#define ASM_QL 81920
#define ATT_SMEM 90112

__global__ void __launch_bounds__(256)
attn_mma_kernel()
{
    extern __shared__ char sm[];
    const uint32_t sb = smem_u32(sm);
    const int w = blockIdx.x / NHEAD;
    const int h = blockIdx.x % NHEAD;
    const int tid = threadIdx.x, lane = tid & 31, wid = tid >> 5;
    const int gid = lane >> 2, tig = lane & 3;

    // zero K/V region (covers pad rows 343..383)
    uint4 z4 = make_uint4(0, 0, 0, 0);
    for (int i = tid; i < 73728 / 16; i += 256)
        reinterpret_cast<uint4*>(sm)[i] = z4;
    __syncthreads();

    // stage K (hi+lo) and V (hi) for this (window, head)
    {
        const __nv_bfloat16* kh = g_KVh + (size_t)(w * NTOK) * C2 + h * HD;
        const __nv_bfloat16* kl = g_KVl + (size_t)(w * NTOK) * C2 + h * HD;
        const __nv_bfloat16* vh = kh + C_DIM;
        for (int i = tid; i < NTOK * 4; i += 256) {
            int row = i >> 2, c = i & 3;
            uint32_t so = swz(row, c);
            size_t go = (size_t)row * C2 + c * 8;
            cp16(sb + ASM_KH + so, kh + go);
            cp16(sb + ASM_KL + so, kl + go);
            cp16(sb + ASM_VH + so, vh + go);
        }
        CP_COMMIT();
    }
    asm volatile("cp.async.wait_group 0;" ::: "memory");
    __syncthreads();

    const float scale = 0.17677669529663687f; // 1/sqrt(32)
    const float* bb = g_bias + (size_t)h * NTOK * BSTR;

    for (int qs = 0; qs < 3; qs++) {
        int q0 = qs * 128;
        // stage Q supertile (128 rows)
        {
            const __nv_bfloat16* qh = g_Qh + ((size_t)(w * NTOK + q0)) * C_DIM + h * HD;
            const __nv_bfloat16* ql = g_Ql + ((size_t)(w * NTOK + q0)) * C_DIM + h * HD;
            for (int i = tid; i < 512; i += 256) {
                int row = i >> 2, c = i & 3;
                uint32_t soh = sb + ASM_QH + swz(row, c);
                uint32_t sol = sb + ASM_QL + swz(row, c);
                if (q0 + row < NTOK) {
                    size_t go = (size_t)row * C_DIM + c * 8;
                    cp16(soh, qh + go);
                    cp16(sol, ql + go);
                } else {
                    ZERO16(soh);
                    ZERO16(sol);
                }
            }
            CP_COMMIT();
        }
        asm volatile("cp.async.wait_group 0;" ::: "memory");
        __syncthreads();

        // Q fragments (warp owns 16 rows)
        uint32_t qfh[2][4], qfl[2][4];
#pragma unroll
        for (int ks = 0; ks < 2; ks++) {
            uint32_t row = wid * 16 + (lane & 15);
            uint32_t c = 2 * ks + (lane >> 4);
            uint32_t ah = sb + ASM_QH + swz(row, c);
            uint32_t al = sb + ASM_QL + swz(row, c);
            LDMX4(qfh[ks][0], qfh[ks][1], qfh[ks][2], qfh[ks][3], ah);
            LDMX4(qfl[ks][0], qfl[ks][1], qfl[ks][2], qfl[ks][3], al);
        }
        __syncthreads();   // all warps done reading Q smem before next restage

        int qrow0 = q0 + wid * 16 + gid;
        int qrow1 = qrow0 + 8;
        bool rv0 = qrow0 < NTOK, rv1 = qrow1 < NTOK;
        float m0 = -1e30f, m1 = -1e30f, l0 = 0.f, l1 = 0.f;
        float oacc[4][4];
#pragma unroll
        for (int o = 0; o < 4; o++)
#pragma unroll
            for (int v = 0; v < 4; v++) oacc[o][v] = 0.f;

        for (int kt = 0; kt < 6; kt++) {
            int t0 = kt * 64;
            float sacc[8][4];
#pragma unroll
            for (int n = 0; n < 8; n++)
#pragma unroll
                for (int v = 0; v < 4; v++) sacc[n][v] = 0.f;

            // S = Q K^T (3-product split), passes reordered to break acc RAW chains
#pragma unroll
            for (int ks = 0; ks < 2; ks++) {
                uint32_t krow = t0 + (lane & 7);
                uint32_t kc = 2 * ks + ((lane >> 3) & 1);
                uint32_t kh[8][2], kl[8][2];
#pragma unroll
                for (int nb = 0; nb < 8; nb++) {
                    uint32_t ad = swz(krow + nb * 8, kc);
                    LDMX2(kh[nb][0], kh[nb][1], sb + ASM_KH + ad);
                    LDMX2(kl[nb][0], kl[nb][1], sb + ASM_KL + ad);
                }
#pragma unroll
                for (int nb = 0; nb < 8; nb++)
                    MMA16816(sacc[nb], qfh[ks], kh[nb]);
#pragma unroll
                for (int nb = 0; nb < 8; nb++)
                    MMA16816(sacc[nb], qfh[ks], kl[nb]);
#pragma unroll
                for (int nb = 0; nb < 8; nb++)
                    MMA16816(sacc[nb], qfl[ks], kh[nb]);
            }

            // scale + bias + mask, row max
            float rmax0 = -1e30f, rmax1 = -1e30f;
#pragma unroll
            for (int nb = 0; nb < 8; nb++) {
                int col = t0 + nb * 8 + tig * 2;
                if (col < NTOK) {
                    bool c1 = (col + 1 < NTOK);
                    float2 b0 = rv0 ? *(const float2*)(bb + (size_t)qrow0 * BSTR + col)
                                    : make_float2(0.f, 0.f);
                    float2 b1 = rv1 ? *(const float2*)(bb + (size_t)qrow1 * BSTR + col)
                                    : make_float2(0.f, 0.f);
                    sacc[nb][0] = sacc[nb][0] * scale + b0.x;
                    sacc[nb][1] = c1 ? sacc[nb][1] * scale + b0.y : -1e30f;
                    sacc[nb][2] = sacc[nb][2] * scale + b1.x;
                    sacc[nb][3] = c1 ? sacc[nb][3] * scale + b1.y : -1e30f;
                } else {
                    sacc[nb][0] = sacc[nb][1] = sacc[nb][2] = sacc[nb][3] = -1e30f;
                }
                rmax0 = fmaxf(rmax0, fmaxf(sacc[nb][0], sacc[nb][1]));
                rmax1 = fmaxf(rmax1, fmaxf(sacc[nb][2], sacc[nb][3]));
            }
            rmax0 = fmaxf(rmax0, __shfl_xor_sync(0xffffffffu, rmax0, 1));
            rmax0 = fmaxf(rmax0, __shfl_xor_sync(0xffffffffu, rmax0, 2));
            rmax1 = fmaxf(rmax1, __shfl_xor_sync(0xffffffffu, rmax1, 1));
            rmax1 = fmaxf(rmax1, __shfl_xor_sync(0xffffffffu, rmax1, 2));

            float mn0 = fmaxf(m0, rmax0), mn1 = fmaxf(m1, rmax1);
            float sc0 = __expf(m0 - mn0), sc1 = __expf(m1 - mn1);
            m0 = mn0; m1 = mn1;

            float rs0 = 0.f, rs1 = 0.f;
#pragma unroll
            for (int nb = 0; nb < 8; nb++) {
                sacc[nb][0] = __expf(sacc[nb][0] - m0);
                sacc[nb][1] = __expf(sacc[nb][1] - m0);
                sacc[nb][2] = __expf(sacc[nb][2] - m1);
                sacc[nb][3] = __expf(sacc[nb][3] - m1);
                rs0 += sacc[nb][0] + sacc[nb][1];
                rs1 += sacc[nb][2] + sacc[nb][3];
            }
            rs0 += __shfl_xor_sync(0xffffffffu, rs0, 1);
            rs0 += __shfl_xor_sync(0xffffffffu, rs0, 2);
            rs1 += __shfl_xor_sync(0xffffffffu, rs1, 1);
            rs1 += __shfl_xor_sync(0xffffffffu, rs1, 2);
            l0 = l0 * sc0 + rs0;
            l1 = l1 * sc1 + rs1;
#pragma unroll
            for (int o = 0; o < 4; o++) {
                oacc[o][0] *= sc0; oacc[o][1] *= sc0;
                oacc[o][2] *= sc1; oacc[o][3] *= sc1;
            }

            // O += P V  (P split hi/lo, V hi only); hi pass then lo pass
#pragma unroll
            for (int ks2 = 0; ks2 < 4; ks2++) {
                float* f0 = sacc[2 * ks2];
                float* f1 = sacc[2 * ks2 + 1];
                float h00 = tobf(f0[0]), h01 = tobf(f0[1]), h02 = tobf(f0[2]), h03 = tobf(f0[3]);
                float h10 = tobf(f1[0]), h11 = tobf(f1[1]), h12 = tobf(f1[2]), h13 = tobf(f1[3]);
                uint32_t pah[4], pal[4];
                pah[0] = packbf(h00, h01);
                pah[1] = packbf(h02, h03);
                pah[2] = packbf(h10, h11);
                pah[3] = packbf(h12, h13);
                pal[0] = packbf(f0[0] - h00, f0[1] - h01);
                pal[1] = packbf(f0[2] - h02, f0[3] - h03);
                pal[2] = packbf(f1[0] - h10, f1[1] - h11);
                pal[3] = packbf(f1[2] - h12, f1[3] - h13);
                uint32_t vrow = t0 + ks2 * 16 + (lane & 15);
                uint32_t bv[4][2];
#pragma unroll
                for (int onb = 0; onb < 4; onb++)
                    LDMX2T(bv[onb][0], bv[onb][1], sb + ASM_VH + swz(vrow, onb));
#pragma unroll
                for (int onb = 0; onb < 4; onb++)
                    MMA16816(oacc[onb], pah, bv[onb]);
#pragma unroll
                for (int onb = 0; onb < 4; onb++)
                    MMA16816(oacc[onb], pal, bv[onb]);
            }
        } // kt

        float inv0 = 1.f / l0, inv1 = 1.f / l1;
#pragma unroll
        for (int onb = 0; onb < 4; onb++) {
            int ch = h * HD + onb * 8 + tig * 2;
            if (rv0) {
                float x = oacc[onb][0] * inv0, y = oacc[onb][1] * inv0;
                float hx = tobf(x), hy = tobf(y);
                size_t base = ((size_t)(w * NTOK + qrow0)) * C_DIM + ch;
                *(uint32_t*)(g_Oh + base) = packbf(hx, hy);
                *(uint32_t*)(g_Ol + base) = packbf(x - hx, y - hy);
            }
            if (rv1) {
                float x = oacc[onb][2] * inv1, y = oacc[onb][3] * inv1;
                float hx = tobf(x), hy = tobf(y);
                size_t base = ((size_t)(w * NTOK + qrow1)) * C_DIM + ch;
                *(uint32_t*)(g_Oh + base) = packbf(hx, hy);
                *(uint32_t*)(g_Ol + base) = packbf(x - hx, y - hy);
            }
        }
    } // qs
}

// ---------------- LN2 -> Yh/Yl ----------------
__global__ void ln2_kernel(const float* __restrict__ g, const float* __restrict__ b)
{
    int l = blockIdx.x, tid = threadIdx.x;
    const float* row = g_X + (size_t)l * C_DIM;
    float xv[3];
    float s = 0.f, sq = 0.f;
#pragma unroll
    for (int t = 0; t < 3; t++) {
        int c = tid + t * 128;
        float x = row[c];
        xv[t] = x; s += x; sq += x * x;
    }
    __shared__ float red[4][2];
#pragma unroll
    for (int o = 16; o > 0; o >>= 1) {
        s  += __shfl_down_sync(0xffffffffu, s , o);
        sq += __shfl_down_sync(0xffffffffu, sq, o);
    }
    int warp = tid >> 5, lane = tid & 31;
    if (lane == 0) { red[warp][0] = s; red[warp][1] = sq; }
    __syncthreads();
    float S  = red[0][0]+red[1][0]+red[2][0]+red[3][0];
    float SQ = red[0][1]+red[1][1]+red[2][1]+red[3][1];
    const float inv = 1.f / (float)C_DIM;
    float m = S * inv;
    float rs = rsqrtf(SQ * inv - m * m + 1e-5f);
#pragma unroll
    for (int t = 0; t < 3; t++) {
        int c = tid + t * 128;
        float y = (xv[t] - m) * rs * g[c] + b[c];
        __nv_bfloat16 h, lo; bsplit(y, h, lo);
        g_Yh[(size_t)l * C_DIM + c] = h;
        g_Yl[(size_t)l * C_DIM + c] = lo;
    }
}

// ---------------- launch ----------------
extern "C" void kernel_launch(void* const* d_in, const int* in_sizes, int n_in,
                              void* d_out, int out_size)
{
    const float* skip = (const float*)d_in[0];
    const float* x_up = (const float*)d_in[1];
    int o = (n_in >= 18) ? 5 : 2;
    const float* ln1_g  = (const float*)d_in[o + 0];
    const float* ln1_b  = (const float*)d_in[o + 1];
    const float* kv_w   = (const float*)d_in[o + 2];
    const float* kv_b   = (const float*)d_in[o + 3];
    const float* rpb    = (const float*)d_in[o + 4];
    const float* proj_w = (const float*)d_in[o + 5];
    const float* proj_b = (const float*)d_in[o + 6];
    const float* ln2_g  = (const float*)d_in[o + 7];
    const float* ln2_b  = (const float*)d_in[o + 8];
    const float* mlp_w1 = (const float*)d_in[o + 9];
    const float* mlp_b1 = (const float*)d_in[o + 10];
    const float* mlp_w2 = (const float*)d_in[o + 11];
    const float* mlp_b2 = (const float*)d_in[o + 12];
    float* out = (float*)d_out;

    float* pX;
    __nv_bfloat16 *pSKh, *pSKl, *pKVh, *pKVl, *pOh, *pOl, *pYh, *pYl, *pH1h, *pH1l;
    __nv_bfloat16 *pWkvh, *pWkvl, *pWprh, *pWprl, *pW1h, *pW1l, *pW2h, *pW2l;
    cudaGetSymbolAddress((void**)&pX,   g_X);
    cudaGetSymbolAddress((void**)&pSKh, g_SKh); cudaGetSymbolAddress((void**)&pSKl, g_SKl);
    cudaGetSymbolAddress((void**)&pKVh, g_KVh); cudaGetSymbolAddress((void**)&pKVl, g_KVl);
    cudaGetSymbolAddress((void**)&pOh,  g_Oh);  cudaGetSymbolAddress((void**)&pOl,  g_Ol);
    cudaGetSymbolAddress((void**)&pYh,  g_Yh);  cudaGetSymbolAddress((void**)&pYl,  g_Yl);
    cudaGetSymbolAddress((void**)&pH1h, g_H1h); cudaGetSymbolAddress((void**)&pH1l, g_H1l);
    cudaGetSymbolAddress((void**)&pWkvh, g_Wkvh); cudaGetSymbolAddress((void**)&pWkvl, g_Wkvl);
    cudaGetSymbolAddress((void**)&pWprh, g_Wprh); cudaGetSymbolAddress((void**)&pWprl, g_Wprl);
    cudaGetSymbolAddress((void**)&pW1h,  g_W1h);  cudaGetSymbolAddress((void**)&pW1l,  g_W1l);
    cudaGetSymbolAddress((void**)&pW2h,  g_W2h);  cudaGetSymbolAddress((void**)&pW2l,  g_W2l);

    int gemm_smem = 2 * STAGE;  // 64 KB
    cudaFuncSetAttribute(hmma_gemm<0>, cudaFuncAttributeMaxDynamicSharedMemorySize, gemm_smem);
    cudaFuncSetAttribute(hmma_gemm<1>, cudaFuncAttributeMaxDynamicSharedMemorySize, gemm_smem);
    cudaFuncSetAttribute(hmma_gemm<2>, cudaFuncAttributeMaxDynamicSharedMemorySize, gemm_smem);
    cudaFuncSetAttribute(hmma_gemm<3>, cudaFuncAttributeMaxDynamicSharedMemorySize, gemm_smem);
    cudaFuncSetAttribute(attn_mma_kernel, cudaFuncAttributeMaxDynamicSharedMemorySize, ATT_SMEM);

    const int MT = MPAD / GBM;  // 172

    // launch order arranged so launch index 5 (ncu -s 5 -c 1) = KV GEMM for re-profiling
    add_ln1_kernel<<<L_TOK, 128>>>(skip, x_up, ln1_g, ln1_b);                       // 0
    bias_kernel<<<(NHEAD * NTOK * NTOK + 255) / 256, 256>>>(rpb);                   // 1
    wprep_kernel<<<(C_DIM * C2 + 255) / 256, 256>>>(kv_w, pWkvh, pWkvl, C_DIM, C2); // 2
    wprep_kernel<<<(C_DIM * C_DIM + 255) / 256, 256>>>(proj_w, pWprh, pWprl, C_DIM, C_DIM); // 3
    wprep_kernel<<<(C_DIM * C4 + 255) / 256, 256>>>(mlp_w1, pW1h, pW1l, C_DIM, C4); // 4
    hmma_gemm<0><<<dim3(C2 / GBN, MT), 256, gemm_smem>>>(pSKh, pSKl, pWkvh, pWkvl,  // 5 <- profiled
        kv_b, nullptr, pKVh, pKVl, nullptr, C_DIM, C2, L_TOK);
    attn_mma_kernel<<<NWIN * NHEAD, 256, ATT_SMEM>>>();                             // 6
    hmma_gemm<1><<<dim3(C_DIM / GBN, MT), 256, gemm_smem>>>(pOh, pOl, pWprh, pWprl, // 7
        proj_b, pX, nullptr, nullptr, nullptr, C_DIM, C_DIM, L_TOK);
    ln2_kernel<<<L_TOK, 128>>>(ln2_g, ln2_b);                                       // 8
    hmma_gemm<2><<<dim3(C4 / GBN, MT), 256, gemm_smem>>>(pYh, pYl, pW1h, pW1l,      // 9
        mlp_b1, nullptr, pH1h, pH1l, nullptr, C_DIM, C4, L_TOK);
    wprep_kernel<<<(C4 * C_DIM + 255) / 256, 256>>>(mlp_w2, pW2h, pW2l, C4, C_DIM); // 10
    hmma_gemm<3><<<dim3(C_DIM / GBN, MT), 256, gemm_smem>>>(pH1h, pH1l, pW2h, pW2l, // 11
        mlp_b2, out, nullptr, nullptr, pX, C4, C_DIM, L_TOK);
}

// round 8
// speedup vs baseline: 6.0957x; 2.1251x over previous
#include <cuda_runtime.h>
#include <cuda_fp16.h>
#include <math.h>
#include <stdint.h>

#define L_TOK 21952
#define MPAD  22016
#define C_DIM 384
#define C2    768
#define C4    1536
#define NHEAD 12
#define HD    32
#define NWIN  64
#define NTOK  343
#define BSTR  344   // padded bias row stride

// ---------------- scratch (device globals) ----------------
__device__ float g_X [(size_t)L_TOK * C_DIM];
__device__ __half g_Qf [(size_t)L_TOK * C_DIM];
__device__ __half g_KVf[(size_t)MPAD * C2];
__device__ __half g_SKf[(size_t)MPAD * C_DIM];
__device__ __half g_Of [(size_t)MPAD * C_DIM];
__device__ __half g_Yf [(size_t)MPAD * C_DIM];
__device__ __half g_H1f[(size_t)MPAD * C4];
__device__ float g_bias[NHEAD * NTOK * BSTR];
// weights transposed to [N][K] row-major fp16
__device__ __half g_Wkv[C2 * C_DIM];
__device__ __half g_Wpr[C_DIM * C_DIM];
__device__ __half g_W1 [C4 * C_DIM];
__device__ __half g_W2 [C_DIM * C4];

// ---------------- helpers ----------------
__device__ __forceinline__ uint32_t smem_u32(const void* p) {
    uint32_t a;
    asm("{ .reg .u64 t; cvta.to.shared.u64 t, %1; cvt.u32.u64 %0, t; }" : "=r"(a) : "l"(p));
    return a;
}
// pack two floats as f16x2: first arg -> LOW half
__device__ __forceinline__ uint32_t packh(float lo_, float hi_) {
    uint32_t r;
    asm("cvt.rn.f16x2.f32 %0, %1, %2;" : "=r"(r) : "f"(hi_), "f"(lo_));
    return r;
}

// swizzled smem offset for tiles with 64B rows (4 x 16B chunks per row)
__device__ __forceinline__ uint32_t swz(uint32_t row, uint32_t c) {
    return row * 64u + ((c ^ ((row >> 1) & 3u)) << 4);
}
__device__ __forceinline__ void cp16(uint32_t sm, const void* gm) {
    asm volatile("cp.async.cg.shared.global [%0], [%1], 16;" :: "r"(sm), "l"(gm));
}
#define CP_COMMIT() asm volatile("cp.async.commit_group;" ::: "memory")
#define ZERO16(addr) asm volatile("st.shared.v4.b32 [%0], {%1,%1,%1,%1};" :: "r"(addr), "r"(0u) : "memory")

#define LDMX4(r0, r1, r2, r3, addr) \
    asm volatile("ldmatrix.sync.aligned.m8n8.x4.shared.b16 {%0,%1,%2,%3}, [%4];" \
        : "=r"(r0), "=r"(r1), "=r"(r2), "=r"(r3) : "r"(addr))
#define LDMX2(r0, r1, addr) \
    asm volatile("ldmatrix.sync.aligned.m8n8.x2.shared.b16 {%0,%1}, [%2];" \
        : "=r"(r0), "=r"(r1) : "r"(addr))
#define LDMX2T(r0, r1, addr) \
    asm volatile("ldmatrix.sync.aligned.m8n8.x2.trans.shared.b16 {%0,%1}, [%2];" \
        : "=r"(r0), "=r"(r1) : "r"(addr))

#define MMA16816(d, a, b) \
    asm volatile("mma.sync.aligned.m16n8k16.row.col.f32.f16.f16.f32 " \
        "{%0,%1,%2,%3}, {%4,%5,%6,%7}, {%8,%9}, {%0,%1,%2,%3};" \
        : "+f"((d)[0]), "+f"((d)[1]), "+f"((d)[2]), "+f"((d)[3]) \
        : "r"((a)[0]), "r"((a)[1]), "r"((a)[2]), "r"((a)[3]), \
          "r"((b)[0]), "r"((b)[1]))

// ---------------- kernel 1: x = skip + x_up ; LN1(skip)->SKf ; LN1(x_up)->Qf ----------------
__global__ void add_ln1_kernel(const float* __restrict__ skip,
                               const float* __restrict__ xup,
                               const float* __restrict__ g,
                               const float* __restrict__ b)
{
    int l = blockIdx.x, tid = threadIdx.x;
    const float* srow = skip + (size_t)l * C_DIM;
    const float* urow = xup  + (size_t)l * C_DIM;
    float sv[3], uv[3];
    float ssum = 0.f, ssq = 0.f, usum = 0.f, usq = 0.f;
#pragma unroll
    for (int t = 0; t < 3; t++) {
        int c = tid + t * 128;
        float s = srow[c], u = urow[c];
        sv[t] = s; uv[t] = u;
        g_X[(size_t)l * C_DIM + c] = s + u;
        ssum += s; ssq += s * s; usum += u; usq += u * u;
    }
    __shared__ float red[4][4];
#pragma unroll
    for (int o = 16; o > 0; o >>= 1) {
        ssum += __shfl_down_sync(0xffffffffu, ssum, o);
        ssq  += __shfl_down_sync(0xffffffffu, ssq , o);
        usum += __shfl_down_sync(0xffffffffu, usum, o);
        usq  += __shfl_down_sync(0xffffffffu, usq , o);
    }
    int warp = tid >> 5, lane = tid & 31;
    if (lane == 0) { red[warp][0]=ssum; red[warp][1]=ssq; red[warp][2]=usum; red[warp][3]=usq; }
    __syncthreads();
    float S  = red[0][0]+red[1][0]+red[2][0]+red[3][0];
    float SQ = red[0][1]+red[1][1]+red[2][1]+red[3][1];
    float U  = red[0][2]+red[1][2]+red[2][2]+red[3][2];
    float UQ = red[0][3]+red[1][3]+red[2][3]+red[3][3];
    const float inv = 1.f / (float)C_DIM;
    float ms = S * inv, vs = SQ * inv - ms * ms;
    float mu = U * inv, vu = UQ * inv - mu * mu;
    float rs = rsqrtf(vs + 1e-5f), ru = rsqrtf(vu + 1e-5f);

    int d = l / 784, rem = l % 784, hh = rem / 28, ww = rem % 28;
    int widx = ((d / 7) * 4 + hh / 7) * 4 + ww / 7;
    int nidx = ((d % 7) * 7 + hh % 7) * 7 + ww % 7;
    size_t wrow = (size_t)(widx * NTOK + nidx) * C_DIM;
#pragma unroll
    for (int t = 0; t < 3; t++) {
        int c = tid + t * 128;
        float gg = g[c], bb = b[c];
        g_SKf[wrow + c] = __float2half((sv[t] - ms) * rs * gg + bb);
        g_Qf [wrow + c] = __float2half((uv[t] - mu) * ru * gg + bb);
    }
}

// ---------------- kernel 2: expand relative position bias (stride 344) ----------------
__global__ void bias_kernel(const float* __restrict__ rpb)
{
    int i = blockIdx.x * blockDim.x + threadIdx.x;
    if (i >= NHEAD * NTOK * NTOK) return;
    int h = i / (NTOK * NTOK);
    int r = i % (NTOK * NTOK);
    int q = r / NTOK, k = r % NTOK;
    int z1 = q / 49, y1 = (q / 7) % 7, x1 = q % 7;
    int z2 = k / 49, y2 = (k / 7) % 7, x2 = k % 7;
    int rel = (z1 - z2 + 6) * 169 + (y1 - y2 + 6) * 13 + (x1 - x2 + 6);
    g_bias[((size_t)h * NTOK + q) * BSTR + k] = rpb[rel * NHEAD + h];
}

// ---------------- weight prep: W[K][N] fp32 -> Wt [N][K] fp16 ----------------
__global__ void wprep_kernel(const float* __restrict__ W,
                             __half* __restrict__ T, int K, int N)
{
    int i = blockIdx.x * blockDim.x + threadIdx.x;
    if (i >= K * N) return;
    int n = i / K, k = i % K;
    T[i] = __float2half(W[(size_t)k * N + n]);
}

// ---------------- mma.sync GEMM: C[M,N] = A @ Bt^T  (Bt is [N][K]) fp16 single ----------------
// EPI 0: fp16 store (KV)   1: proj scatter-add residual into g_X (window reverse)
// EPI 2: gelu -> fp16      3: out = Xres + v (bounded)
#define GBM 128
#define GBN 128
#define GBK 32
#define STAGE 16384   // A 8K | B 8K

template <int EPI>
__global__ void __launch_bounds__(256, 2)
hmma_gemm(const __half* __restrict__ A, const __half* __restrict__ B,
          const float* __restrict__ bias, float* __restrict__ Cf,
          __half* __restrict__ Ch,
          const float* __restrict__ Xres, int K, int N, int Mvalid)
{
    extern __shared__ char smem[];
    const int tid = threadIdx.x, lane = tid & 31, wid = tid >> 5;
    const int rowBase = blockIdx.y * GBM, colBase = blockIdx.x * GBN;
    const int wM = (wid & 3) * 32, wN = (wid >> 2) * 64;
    const uint32_t sbase = smem_u32(smem);

    float acc[2][8][4];
#pragma unroll
    for (int m = 0; m < 2; m++)
#pragma unroll
        for (int n = 0; n < 8; n++)
#pragma unroll
            for (int v = 0; v < 4; v++) acc[m][n][v] = 0.f;

    const int NC = K / GBK;

    auto issue = [&](int ch) {
        uint32_t sb = sbase + (ch & 1) * STAGE;
        int k0 = ch * GBK;
#pragma unroll
        for (int i = 0; i < 2; i++) {
            int ci = tid + i * 256;
            int r = ci >> 2, c = ci & 3;
            uint32_t so = swz(r, c);
            cp16(sb +        so, A + (size_t)(rowBase + r) * K + k0 + c * 8);
            cp16(sb + 8192 + so, B + (size_t)(colBase + r) * K + k0 + c * 8);
        }
        CP_COMMIT();
    };

    issue(0);
    for (int ch = 0; ch < NC; ch++) {
        if (ch + 1 < NC) {
            issue(ch + 1);
            asm volatile("cp.async.wait_group 1;" ::: "memory");
        } else {
            asm volatile("cp.async.wait_group 0;" ::: "memory");
        }
        __syncthreads();
        uint32_t sb = sbase + (ch & 1) * STAGE;

#pragma unroll
        for (int ks = 0; ks < 2; ks++) {
            uint32_t af[2][4];
#pragma unroll
            for (int m = 0; m < 2; m++) {
                uint32_t row = wM + m * 16 + (lane & 15);
                uint32_t c = ks * 2 + (lane >> 4);
                LDMX4(af[m][0], af[m][1], af[m][2], af[m][3], sb + swz(row, c));
            }
            uint32_t bf[8][2];
#pragma unroll
            for (int nb = 0; nb < 4; nb++) {
                uint32_t row = wN + nb * 16 + (lane & 7) + ((lane >> 4) & 1) * 8;
                uint32_t c = ks * 2 + ((lane >> 3) & 1);
                uint32_t bd = sb + 8192 + swz(row, c);
                LDMX4(bf[nb*2][0], bf[nb*2][1], bf[nb*2+1][0], bf[nb*2+1][1], bd);
            }
#pragma unroll
            for (int m = 0; m < 2; m++)
#pragma unroll
                for (int n = 0; n < 8; n++)
                    MMA16816(acc[m][n], af[m], bf[n]);
        }
        __syncthreads();
    }

    const int gid = lane >> 2, tig = lane & 3;
#pragma unroll
    for (int m = 0; m < 2; m++) {
#pragma unroll
        for (int rr = 0; rr < 2; rr++) {
            int row = rowBase + wM + m * 16 + gid + rr * 8;
            if (EPI == 0) {
#pragma unroll
                for (int n = 0; n < 8; n++) {
                    int col = colBase + wN + n * 8 + tig * 2;
                    float vx = acc[m][n][rr * 2 + 0] + bias[col];
                    float vy = acc[m][n][rr * 2 + 1] + bias[col + 1];
                    *(uint32_t*)(Ch + (size_t)row * N + col) = packh(vx, vy);
                }
            } else if (EPI == 1) {
                if (row < Mvalid) {
                    int widx = row / NTOK, nn = row % NTOK;
                    int dd =  (widx >> 4)      * 7 + nn / 49;
                    int hh = ((widx >> 2) & 3) * 7 + (nn / 7) % 7;
                    int ww =  (widx & 3)       * 7 + nn % 7;
                    int lrow = (dd * 28 + hh) * 28 + ww;
#pragma unroll
                    for (int n = 0; n < 8; n++) {
                        int col = colBase + wN + n * 8 + tig * 2;
                        float* p = Cf + (size_t)lrow * N + col;
                        p[0] += acc[m][n][rr * 2 + 0] + bias[col];
                        p[1] += acc[m][n][rr * 2 + 1] + bias[col + 1];
                    }
                }
            } else if (EPI == 2) {
#pragma unroll
                for (int n = 0; n < 8; n++) {
                    int col = colBase + wN + n * 8 + tig * 2;
                    float gv[2];
#pragma unroll
                    for (int j = 0; j < 2; j++) {
                        float v = acc[m][n][rr * 2 + j] + bias[col + j];
                        float t = tanhf(0.7978845608028654f * (v + 0.044715f * v * v * v));
                        gv[j] = 0.5f * v * (1.f + t);
                    }
                    *(uint32_t*)(Ch + (size_t)row * N + col) = packh(gv[0], gv[1]);
                }
            } else {
                if (row < Mvalid) {
#pragma unroll
                    for (int n = 0; n < 8; n++) {
                        int col = colBase + wN + n * 8 + tig * 2;
                        const float* xr = Xres + (size_t)row * N + col;
                        float2 v;
                        v.x = xr[0] + acc[m][n][rr * 2 + 0] + bias[col];
                        v.y = xr[1] + acc[m][n][rr * 2 + 1] + bias[col + 1];
                        *(float2*)(Cf + (size_t)row * N + col) = v;
                    }
                }
            }
        }
    }
}

// ---------------- flash attention, mma.sync fp16, per (window, head) ----------------
// smem: K[384x32] 24576B | V[384x32] 24576B | Q[128x32] 8192B
#define ASM_K 0
#define ASM_V 24576
#define ASM_Q 49152
#define ATT_SMEM 57344

__global__ void __launch_bounds__(256)
attn_mma_kernel()
{
    extern __shared__ char sm[];
    const uint32_t sb = smem_u32(sm);
    const int w = blockIdx.x / NHEAD;
    const int h = blockIdx.x % NHEAD;
    const int tid = threadIdx.x, lane = tid & 31, wid = tid >> 5;
    const int gid = lane >> 2, tig = lane & 3;

    // zero K/V region (covers pad rows 343..383)
    uint4 z4 = make_uint4(0, 0, 0, 0);
    for (int i = tid; i < 49152 / 16; i += 256)
        reinterpret_cast<uint4*>(sm)[i] = z4;
    __syncthreads();

    // stage K and V for this (window, head)
    {
        const __half* kp = g_KVf + (size_t)(w * NTOK) * C2 + h * HD;
        const __half* vp = kp + C_DIM;
        for (int i = tid; i < NTOK * 4; i += 256) {
            int row = i >> 2, c = i & 3;
            uint32_t so = swz(row, c);
            size_t go = (size_t)row * C2 + c * 8;
            cp16(sb + ASM_K + so, kp + go);
            cp16(sb + ASM_V + so, vp + go);
        }
        CP_COMMIT();
    }
    asm volatile("cp.async.wait_group 0;" ::: "memory");
    __syncthreads();

    const float scale = 0.17677669529663687f; // 1/sqrt(32)
    const float* bb = g_bias + (size_t)h * NTOK * BSTR;

    for (int qs = 0; qs < 3; qs++) {
        int q0 = qs * 128;
        // stage Q supertile (128 rows)
        {
            const __half* qp = g_Qf + ((size_t)(w * NTOK + q0)) * C_DIM + h * HD;
            for (int i = tid; i < 512; i += 256) {
                int row = i >> 2, c = i & 3;
                uint32_t so = sb + ASM_Q + swz(row, c);
                if (q0 + row < NTOK) cp16(so, qp + (size_t)row * C_DIM + c * 8);
                else ZERO16(so);
            }
            CP_COMMIT();
        }
        asm volatile("cp.async.wait_group 0;" ::: "memory");
        __syncthreads();

        // Q fragments (warp owns 16 rows)
        uint32_t qf[2][4];
#pragma unroll
        for (int ks = 0; ks < 2; ks++) {
            uint32_t row = wid * 16 + (lane & 15);
            uint32_t c = 2 * ks + (lane >> 4);
            LDMX4(qf[ks][0], qf[ks][1], qf[ks][2], qf[ks][3], sb + ASM_Q + swz(row, c));
        }
        __syncthreads();   // all warps done reading Q smem before next restage

        int qrow0 = q0 + wid * 16 + gid;
        int qrow1 = qrow0 + 8;
        bool rv0 = qrow0 < NTOK, rv1 = qrow1 < NTOK;
        float m0 = -1e30f, m1 = -1e30f, l0 = 0.f, l1 = 0.f;
        float oacc[4][4];
#pragma unroll
        for (int o = 0; o < 4; o++)
#pragma unroll
            for (int v = 0; v < 4; v++) oacc[o][v] = 0.f;

        for (int kt = 0; kt < 6; kt++) {
            int t0 = kt * 64;
            float sacc[8][4];
#pragma unroll
            for (int n = 0; n < 8; n++)
#pragma unroll
                for (int v = 0; v < 4; v++) sacc[n][v] = 0.f;

            // S = Q K^T
#pragma unroll
            for (int ks = 0; ks < 2; ks++) {
                uint32_t krow = t0 + (lane & 7);
                uint32_t kc = 2 * ks + ((lane >> 3) & 1);
                uint32_t kf[8][2];
#pragma unroll
                for (int nb = 0; nb < 8; nb++)
                    LDMX2(kf[nb][0], kf[nb][1], sb + ASM_K + swz(krow + nb * 8, kc));
#pragma unroll
                for (int nb = 0; nb < 8; nb++)
                    MMA16816(sacc[nb], qf[ks], kf[nb]);
            }

            // scale + bias + mask, row max
            float rmax0 = -1e30f, rmax1 = -1e30f;
#pragma unroll
            for (int nb = 0; nb < 8; nb++) {
                int col = t0 + nb * 8 + tig * 2;
                if (col < NTOK) {
                    bool c1 = (col + 1 < NTOK);
                    float2 b0 = rv0 ? *(const float2*)(bb + (size_t)qrow0 * BSTR + col)
                                    : make_float2(0.f, 0.f);
                    float2 b1 = rv1 ? *(const float2*)(bb + (size_t)qrow1 * BSTR + col)
                                    : make_float2(0.f, 0.f);
                    sacc[nb][0] = sacc[nb][0] * scale + b0.x;
                    sacc[nb][1] = c1 ? sacc[nb][1] * scale + b0.y : -1e30f;
                    sacc[nb][2] = sacc[nb][2] * scale + b1.x;
                    sacc[nb][3] = c1 ? sacc[nb][3] * scale + b1.y : -1e30f;
                } else {
                    sacc[nb][0] = sacc[nb][1] = sacc[nb][2] = sacc[nb][3] = -1e30f;
                }
                rmax0 = fmaxf(rmax0, fmaxf(sacc[nb][0], sacc[nb][1]));
                rmax1 = fmaxf(rmax1, fmaxf(sacc[nb][2], sacc[nb][3]));
            }
            rmax0 = fmaxf(rmax0, __shfl_xor_sync(0xffffffffu, rmax0, 1));
            rmax0 = fmaxf(rmax0, __shfl_xor_sync(0xffffffffu, rmax0, 2));
            rmax1 = fmaxf(rmax1, __shfl_xor_sync(0xffffffffu, rmax1, 1));
            rmax1 = fmaxf(rmax1, __shfl_xor_sync(0xffffffffu, rmax1, 2));

            float mn0 = fmaxf(m0, rmax0), mn1 = fmaxf(m1, rmax1);
            float sc0 = __expf(m0 - mn0), sc1 = __expf(m1 - mn1);
            m0 = mn0; m1 = mn1;

            float rs0 = 0.f, rs1 = 0.f;
#pragma unroll
            for (int nb = 0; nb < 8; nb++) {
                sacc[nb][0] = __expf(sacc[nb][0] - m0);
                sacc[nb][1] = __expf(sacc[nb][1] - m0);
                sacc[nb][2] = __expf(sacc[nb][2] - m1);
                sacc[nb][3] = __expf(sacc[nb][3] - m1);
                rs0 += sacc[nb][0] + sacc[nb][1];
                rs1 += sacc[nb][2] + sacc[nb][3];
            }
            rs0 += __shfl_xor_sync(0xffffffffu, rs0, 1);
            rs0 += __shfl_xor_sync(0xffffffffu, rs0, 2);
            rs1 += __shfl_xor_sync(0xffffffffu, rs1, 1);
            rs1 += __shfl_xor_sync(0xffffffffu, rs1, 2);
            l0 = l0 * sc0 + rs0;
            l1 = l1 * sc1 + rs1;
#pragma unroll
            for (int o = 0; o < 4; o++) {
                oacc[o][0] *= sc0; oacc[o][1] *= sc0;
                oacc[o][2] *= sc1; oacc[o][3] *= sc1;
            }

            // O += P V (P fp16 single)
#pragma unroll
            for (int ks2 = 0; ks2 < 4; ks2++) {
                float* f0 = sacc[2 * ks2];
                float* f1 = sacc[2 * ks2 + 1];
                uint32_t pa[4];
                pa[0] = packh(f0[0], f0[1]);
                pa[1] = packh(f0[2], f0[3]);
                pa[2] = packh(f1[0], f1[1]);
                pa[3] = packh(f1[2], f1[3]);
                uint32_t vrow = t0 + ks2 * 16 + (lane & 15);
                uint32_t bv[4][2];
#pragma unroll
                for (int onb = 0; onb < 4; onb++)
                    LDMX2T(bv[onb][0], bv[onb][1], sb + ASM_V + swz(vrow, onb));
#pragma unroll
                for (int onb = 0; onb < 4; onb++)
                    MMA16816(oacc[onb], pa, bv[onb]);
            }
        } // kt

        float inv0 = 1.f / l0, inv1 = 1.f / l1;
#pragma unroll
        for (int onb = 0; onb < 4; onb++) {
            int ch = h * HD + onb * 8 + tig * 2;
            if (rv0) {
                size_t base = ((size_t)(w * NTOK + qrow0)) * C_DIM + ch;
                *(uint32_t*)(g_Of + base) = packh(oacc[onb][0] * inv0, oacc[onb][1] * inv0);
            }
            if (rv1) {
                size_t base = ((size_t)(w * NTOK + qrow1)) * C_DIM + ch;
                *(uint32_t*)(g_Of + base) = packh(oacc[onb][2] * inv1, oacc[onb][3] * inv1);
            }
        }
    } // qs
}

// ---------------- LN2 -> Yf ----------------
__global__ void ln2_kernel(const float* __restrict__ g, const float* __restrict__ b)
{
    int l = blockIdx.x, tid = threadIdx.x;
    const float* row = g_X + (size_t)l * C_DIM;
    float xv[3];
    float s = 0.f, sq = 0.f;
#pragma unroll
    for (int t = 0; t < 3; t++) {
        int c = tid + t * 128;
        float x = row[c];
        xv[t] = x; s += x; sq += x * x;
    }
    __shared__ float red[4][2];
#pragma unroll
    for (int o = 16; o > 0; o >>= 1) {
        s  += __shfl_down_sync(0xffffffffu, s , o);
        sq += __shfl_down_sync(0xffffffffu, sq, o);
    }
    int warp = tid >> 5, lane = tid & 31;
    if (lane == 0) { red[warp][0] = s; red[warp][1] = sq; }
    __syncthreads();
    float S  = red[0][0]+red[1][0]+red[2][0]+red[3][0];
    float SQ = red[0][1]+red[1][1]+red[2][1]+red[3][1];
    const float inv = 1.f / (float)C_DIM;
    float m = S * inv;
    float rs = rsqrtf(SQ * inv - m * m + 1e-5f);
#pragma unroll
    for (int t = 0; t < 3; t++) {
        int c = tid + t * 128;
        g_Yf[(size_t)l * C_DIM + c] = __float2half((xv[t] - m) * rs * g[c] + b[c]);
    }
}

// ---------------- launch ----------------
extern "C" void kernel_launch(void* const* d_in, const int* in_sizes, int n_in,
                              void* d_out, int out_size)
{
    const float* skip = (const float*)d_in[0];
    const float* x_up = (const float*)d_in[1];
    int o = (n_in >= 18) ? 5 : 2;
    const float* ln1_g  = (const float*)d_in[o + 0];
    const float* ln1_b  = (const float*)d_in[o + 1];
    const float* kv_w   = (const float*)d_in[o + 2];
    const float* kv_b   = (const float*)d_in[o + 3];
    const float* rpb    = (const float*)d_in[o + 4];
    const float* proj_w = (const float*)d_in[o + 5];
    const float* proj_b = (const float*)d_in[o + 6];
    const float* ln2_g  = (const float*)d_in[o + 7];
    const float* ln2_b  = (const float*)d_in[o + 8];
    const float* mlp_w1 = (const float*)d_in[o + 9];
    const float* mlp_b1 = (const float*)d_in[o + 10];
    const float* mlp_w2 = (const float*)d_in[o + 11];
    const float* mlp_b2 = (const float*)d_in[o + 12];
    float* out = (float*)d_out;

    float* pX;
    __half *pSK, *pKV, *pO, *pY, *pH1, *pWkv, *pWpr, *pW1, *pW2;
    cudaGetSymbolAddress((void**)&pX,   g_X);
    cudaGetSymbolAddress((void**)&pSK,  g_SKf);
    cudaGetSymbolAddress((void**)&pKV,  g_KVf);
    cudaGetSymbolAddress((void**)&pO,   g_Of);
    cudaGetSymbolAddress((void**)&pY,   g_Yf);
    cudaGetSymbolAddress((void**)&pH1,  g_H1f);
    cudaGetSymbolAddress((void**)&pWkv, g_Wkv);
    cudaGetSymbolAddress((void**)&pWpr, g_Wpr);
    cudaGetSymbolAddress((void**)&pW1,  g_W1);
    cudaGetSymbolAddress((void**)&pW2,  g_W2);

    int gemm_smem = 2 * STAGE;  // 32 KB
    cudaFuncSetAttribute(hmma_gemm<0>, cudaFuncAttributeMaxDynamicSharedMemorySize, gemm_smem);
    cudaFuncSetAttribute(hmma_gemm<1>, cudaFuncAttributeMaxDynamicSharedMemorySize, gemm_smem);
    cudaFuncSetAttribute(hmma_gemm<2>, cudaFuncAttributeMaxDynamicSharedMemorySize, gemm_smem);
    cudaFuncSetAttribute(hmma_gemm<3>, cudaFuncAttributeMaxDynamicSharedMemorySize, gemm_smem);
    cudaFuncSetAttribute(attn_mma_kernel, cudaFuncAttributeMaxDynamicSharedMemorySize, ATT_SMEM);

    const int MT = MPAD / GBM;  // 172

    add_ln1_kernel<<<L_TOK, 128>>>(skip, x_up, ln1_g, ln1_b);                   // 0
    bias_kernel<<<(NHEAD * NTOK * NTOK + 255) / 256, 256>>>(rpb);               // 1
    wprep_kernel<<<(C_DIM * C2 + 255) / 256, 256>>>(kv_w, pWkv, C_DIM, C2);     // 2
    wprep_kernel<<<(C_DIM * C_DIM + 255) / 256, 256>>>(proj_w, pWpr, C_DIM, C_DIM); // 3
    wprep_kernel<<<(C_DIM * C4 + 255) / 256, 256>>>(mlp_w1, pW1, C_DIM, C4);    // 4
    hmma_gemm<0><<<dim3(C2 / GBN, MT), 256, gemm_smem>>>(pSK, pWkv,             // 5 <- profiled
        kv_b, nullptr, pKV, nullptr, C_DIM, C2, L_TOK);
    attn_mma_kernel<<<NWIN * NHEAD, 256, ATT_SMEM>>>();                         // 6
    hmma_gemm<1><<<dim3(C_DIM / GBN, MT), 256, gemm_smem>>>(pO, pWpr,           // 7
        proj_b, pX, nullptr, nullptr, C_DIM, C_DIM, L_TOK);
    ln2_kernel<<<L_TOK, 128>>>(ln2_g, ln2_b);                                   // 8
    hmma_gemm<2><<<dim3(C4 / GBN, MT), 256, gemm_smem>>>(pY, pW1,               // 9
        mlp_b1, nullptr, pH1, nullptr, C_DIM, C4, L_TOK);
    wprep_kernel<<<(C4 * C_DIM + 255) / 256, 256>>>(mlp_w2, pW2, C4, C_DIM);    // 10
    hmma_gemm<3><<<dim3(C_DIM / GBN, MT), 256, gemm_smem>>>(pH1, pW2,           // 11
        mlp_b2, out, nullptr, pX, C4, C_DIM, L_TOK);
}

// round 10
// speedup vs baseline: 6.2191x; 1.0202x over previous
#include <cuda_runtime.h>
#include <cuda_fp16.h>
#include <math.h>
#include <stdint.h>

#define L_TOK 21952
#define MPAD  22016
#define C_DIM 384
#define C2    768
#define C4    1536
#define NHEAD 12
#define HD    32
#define NWIN  64
#define NTOK  343
#define BSTR  344   // padded bias row stride

// ---------------- scratch (device globals) ----------------
__device__ float g_X [(size_t)L_TOK * C_DIM];
__device__ __half g_Qf [(size_t)L_TOK * C_DIM];
__device__ __half g_KVf[(size_t)MPAD * C2];
__device__ __half g_SKf[(size_t)MPAD * C_DIM];
__device__ __half g_Of [(size_t)MPAD * C_DIM];
__device__ __half g_Yf [(size_t)MPAD * C_DIM];
__device__ __half g_H1f[(size_t)MPAD * C4];
__device__ float g_bias[NHEAD * NTOK * BSTR];
// weights transposed to [N][K] row-major fp16
__device__ __half g_Wkv[C2 * C_DIM];
__device__ __half g_Wpr[C_DIM * C_DIM];
__device__ __half g_W1 [C4 * C_DIM];
__device__ __half g_W2 [C_DIM * C4];

// ---------------- helpers ----------------
__device__ __forceinline__ uint32_t smem_u32(const void* p) {
    uint32_t a;
    asm("{ .reg .u64 t; cvta.to.shared.u64 t, %1; cvt.u32.u64 %0, t; }" : "=r"(a) : "l"(p));
    return a;
}
// pack two floats as f16x2: first arg -> LOW half
__device__ __forceinline__ uint32_t packh(float lo_, float hi_) {
    uint32_t r;
    asm("cvt.rn.f16x2.f32 %0, %1, %2;" : "=r"(r) : "f"(hi_), "f"(lo_));
    return r;
}

// swizzled smem offset for tiles with 64B rows (4 x 16B chunks per row)
__device__ __forceinline__ uint32_t swz(uint32_t row, uint32_t c) {
    return row * 64u + ((c ^ ((row >> 1) & 3u)) << 4);
}
__device__ __forceinline__ void cp16(uint32_t sm, const void* gm) {
    asm volatile("cp.async.cg.shared.global [%0], [%1], 16;" :: "r"(sm), "l"(gm));
}
#define CP_COMMIT() asm volatile("cp.async.commit_group;" ::: "memory")
#define ZERO16(addr) asm volatile("st.shared.v4.b32 [%0], {%1,%1,%1,%1};" :: "r"(addr), "r"(0u) : "memory")

#define LDMX4(r0, r1, r2, r3, addr) \
    asm volatile("ldmatrix.sync.aligned.m8n8.x4.shared.b16 {%0,%1,%2,%3}, [%4];" \
        : "=r"(r0), "=r"(r1), "=r"(r2), "=r"(r3) : "r"(addr))
#define LDMX2(r0, r1, addr) \
    asm volatile("ldmatrix.sync.aligned.m8n8.x2.shared.b16 {%0,%1}, [%2];" \
        : "=r"(r0), "=r"(r1) : "r"(addr))
#define LDMX2T(r0, r1, addr) \
    asm volatile("ldmatrix.sync.aligned.m8n8.x2.trans.shared.b16 {%0,%1}, [%2];" \
        : "=r"(r0), "=r"(r1) : "r"(addr))

#define MMA16816(d, a, b) \
    asm volatile("mma.sync.aligned.m16n8k16.row.col.f32.f16.f16.f32 " \
        "{%0,%1,%2,%3}, {%4,%5,%6,%7}, {%8,%9}, {%0,%1,%2,%3};" \
        : "+f"((d)[0]), "+f"((d)[1]), "+f"((d)[2]), "+f"((d)[3]) \
        : "r"((a)[0]), "r"((a)[1]), "r"((a)[2]), "r"((a)[3]), \
          "r"((b)[0]), "r"((b)[1]))

// ---------------- kernel 1: x = skip + x_up ; LN1(skip)->SKf ; LN1(x_up)->Qf ----------------
__global__ void add_ln1_kernel(const float* __restrict__ skip,
                               const float* __restrict__ xup,
                               const float* __restrict__ g,
                               const float* __restrict__ b)
{
    int l = blockIdx.x, tid = threadIdx.x;
    const float* srow = skip + (size_t)l * C_DIM;
    const float* urow = xup  + (size_t)l * C_DIM;
    float sv[3], uv[3];
    float ssum = 0.f, ssq = 0.f, usum = 0.f, usq = 0.f;
#pragma unroll
    for (int t = 0; t < 3; t++) {
        int c = tid + t * 128;
        float s = srow[c], u = urow[c];
        sv[t] = s; uv[t] = u;
        g_X[(size_t)l * C_DIM + c] = s + u;
        ssum += s; ssq += s * s; usum += u; usq += u * u;
    }
    __shared__ float red[4][4];
#pragma unroll
    for (int o = 16; o > 0; o >>= 1) {
        ssum += __shfl_down_sync(0xffffffffu, ssum, o);
        ssq  += __shfl_down_sync(0xffffffffu, ssq , o);
        usum += __shfl_down_sync(0xffffffffu, usum, o);
        usq  += __shfl_down_sync(0xffffffffu, usq , o);
    }
    int warp = tid >> 5, lane = tid & 31;
    if (lane == 0) { red[warp][0]=ssum; red[warp][1]=ssq; red[warp][2]=usum; red[warp][3]=usq; }
    __syncthreads();
    float S  = red[0][0]+red[1][0]+red[2][0]+red[3][0];
    float SQ = red[0][1]+red[1][1]+red[2][1]+red[3][1];
    float U  = red[0][2]+red[1][2]+red[2][2]+red[3][2];
    float UQ = red[0][3]+red[1][3]+red[2][3]+red[3][3];
    const float inv = 1.f / (float)C_DIM;
    float ms = S * inv, vs = SQ * inv - ms * ms;
    float mu = U * inv, vu = UQ * inv - mu * mu;
    float rs = rsqrtf(vs + 1e-5f), ru = rsqrtf(vu + 1e-5f);

    int d = l / 784, rem = l % 784, hh = rem / 28, ww = rem % 28;
    int widx = ((d / 7) * 4 + hh / 7) * 4 + ww / 7;
    int nidx = ((d % 7) * 7 + hh % 7) * 7 + ww % 7;
    size_t wrow = (size_t)(widx * NTOK + nidx) * C_DIM;
#pragma unroll
    for (int t = 0; t < 3; t++) {
        int c = tid + t * 128;
        float gg = g[c], bb = b[c];
        g_SKf[wrow + c] = __float2half((sv[t] - ms) * rs * gg + bb);
        g_Qf [wrow + c] = __float2half((uv[t] - mu) * ru * gg + bb);
    }
}

// ---------------- kernel 2: expand relative position bias (stride 344) ----------------
__global__ void bias_kernel(const float* __restrict__ rpb)
{
    int i = blockIdx.x * blockDim.x + threadIdx.x;
    if (i >= NHEAD * NTOK * NTOK) return;
    int h = i / (NTOK * NTOK);
    int r = i % (NTOK * NTOK);
    int q = r / NTOK, k = r % NTOK;
    int z1 = q / 49, y1 = (q / 7) % 7, x1 = q % 7;
    int z2 = k / 49, y2 = (k / 7) % 7, x2 = k % 7;
    int rel = (z1 - z2 + 6) * 169 + (y1 - y2 + 6) * 13 + (x1 - x2 + 6);
    g_bias[((size_t)h * NTOK + q) * BSTR + k] = rpb[rel * NHEAD + h];
}

// ---------------- weight prep: W[K][N] fp32 -> Wt [N][K] fp16 ----------------
__global__ void wprep_kernel(const float* __restrict__ W,
                             __half* __restrict__ T, int K, int N)
{
    int i = blockIdx.x * blockDim.x + threadIdx.x;
    if (i >= K * N) return;
    int n = i / K, k = i % K;
    T[i] = __float2half(W[(size_t)k * N + n]);
}

// ---------------- mma.sync GEMM: C[M,N] = A @ Bt^T  (Bt is [N][K]) fp16 ----------------
// 128 threads, 4 warps of 64x64 warp-tiles (2M x 2N), CTA tile 128x128, 3-stage cp.async
// EPI 0: fp16 store (KV)   1: proj scatter-add residual into g_X (window reverse)
// EPI 2: gelu -> fp16      3: out = Xres + v (bounded)
#define GBM 128
#define GBN 128
#define GBK 32
#define NSTG 3
#define STAGE 16384   // A 8K | B 8K

template <int EPI>
__global__ void __launch_bounds__(128, 2)
hmma_gemm(const __half* __restrict__ A, const __half* __restrict__ B,
          const float* __restrict__ bias, float* __restrict__ Cf,
          __half* __restrict__ Ch,
          const float* __restrict__ Xres, int K, int N, int Mvalid)
{
    extern __shared__ char smem[];
    const int tid = threadIdx.x, lane = tid & 31, wid = tid >> 5;
    const int rowBase = blockIdx.y * GBM, colBase = blockIdx.x * GBN;
    const int wM = (wid & 1) * 64, wN = (wid >> 1) * 64;
    const uint32_t sbase = smem_u32(smem);

    float acc[4][8][4];
#pragma unroll
    for (int m = 0; m < 4; m++)
#pragma unroll
        for (int n = 0; n < 8; n++)
#pragma unroll
            for (int v = 0; v < 4; v++) acc[m][n][v] = 0.f;

    const int NC = K / GBK;

    auto issue = [&](int ch) {
        uint32_t sb = sbase + (ch % NSTG) * STAGE;
        int k0 = ch * GBK;
#pragma unroll
        for (int i = 0; i < 4; i++) {
            int ci = tid + i * 128;
            int r = ci >> 2, c = ci & 3;
            uint32_t so = swz(r, c);
            cp16(sb +        so, A + (size_t)(rowBase + r) * K + k0 + c * 8);
            cp16(sb + 8192 + so, B + (size_t)(colBase + r) * K + k0 + c * 8);
        }
        CP_COMMIT();
    };

    issue(0);
    if (NC > 1) issue(1);
    for (int ch = 0; ch < NC; ch++) {
        if (ch + 2 < NC) {
            issue(ch + 2);
            asm volatile("cp.async.wait_group 2;" ::: "memory");
        } else if (ch + 1 < NC) {
            asm volatile("cp.async.wait_group 1;" ::: "memory");
        } else {
            asm volatile("cp.async.wait_group 0;" ::: "memory");
        }
        __syncthreads();
        uint32_t sb = sbase + (ch % NSTG) * STAGE;

#pragma unroll
        for (int ks = 0; ks < 2; ks++) {
            uint32_t af[4][4];
#pragma unroll
            for (int mt = 0; mt < 4; mt++) {
                uint32_t row = wM + mt * 16 + (lane & 15);
                uint32_t c = ks * 2 + (lane >> 4);
                LDMX4(af[mt][0], af[mt][1], af[mt][2], af[mt][3], sb + swz(row, c));
            }
            uint32_t bf[8][2];
#pragma unroll
            for (int nb = 0; nb < 4; nb++) {
                uint32_t row = wN + nb * 16 + (lane & 7) + ((lane >> 4) & 1) * 8;
                uint32_t c = ks * 2 + ((lane >> 3) & 1);
                uint32_t bd = sb + 8192 + swz(row, c);
                LDMX4(bf[nb*2][0], bf[nb*2][1], bf[nb*2+1][0], bf[nb*2+1][1], bd);
            }
#pragma unroll
            for (int mt = 0; mt < 4; mt++)
#pragma unroll
                for (int nb = 0; nb < 8; nb++)
                    MMA16816(acc[mt][nb], af[mt], bf[nb]);
        }
        __syncthreads();
    }

    const int gid = lane >> 2, tig = lane & 3;
#pragma unroll
    for (int m = 0; m < 4; m++) {
#pragma unroll
        for (int rr = 0; rr < 2; rr++) {
            int row = rowBase + wM + m * 16 + gid + rr * 8;
            if (EPI == 0) {
#pragma unroll
                for (int n = 0; n < 8; n++) {
                    int col = colBase + wN + n * 8 + tig * 2;
                    float vx = acc[m][n][rr * 2 + 0] + bias[col];
                    float vy = acc[m][n][rr * 2 + 1] + bias[col + 1];
                    *(uint32_t*)(Ch + (size_t)row * N + col) = packh(vx, vy);
                }
            } else if (EPI == 1) {
                if (row < Mvalid) {
                    int widx = row / NTOK, nn = row % NTOK;
                    int dd =  (widx >> 4)      * 7 + nn / 49;
                    int hh = ((widx >> 2) & 3) * 7 + (nn / 7) % 7;
                    int ww =  (widx & 3)       * 7 + nn % 7;
                    int lrow = (dd * 28 + hh) * 28 + ww;
#pragma unroll
                    for (int n = 0; n < 8; n++) {
                        int col = colBase + wN + n * 8 + tig * 2;
                        float* p = Cf + (size_t)lrow * N + col;
                        p[0] += acc[m][n][rr * 2 + 0] + bias[col];
                        p[1] += acc[m][n][rr * 2 + 1] + bias[col + 1];
                    }
                }
            } else if (EPI == 2) {
#pragma unroll
                for (int n = 0; n < 8; n++) {
                    int col = colBase + wN + n * 8 + tig * 2;
                    float gv[2];
#pragma unroll
                    for (int j = 0; j < 2; j++) {
                        float v = acc[m][n][rr * 2 + j] + bias[col + j];
                        float t = tanhf(0.7978845608028654f * (v + 0.044715f * v * v * v));
                        gv[j] = 0.5f * v * (1.f + t);
                    }
                    *(uint32_t*)(Ch + (size_t)row * N + col) = packh(gv[0], gv[1]);
                }
            } else {
                if (row < Mvalid) {
#pragma unroll
                    for (int n = 0; n < 8; n++) {
                        int col = colBase + wN + n * 8 + tig * 2;
                        const float* xr = Xres + (size_t)row * N + col;
                        float2 v;
                        v.x = xr[0] + acc[m][n][rr * 2 + 0] + bias[col];
                        v.y = xr[1] + acc[m][n][rr * 2 + 1] + bias[col + 1];
                        *(float2*)(Cf + (size_t)row * N + col) = v;
                    }
                }
            }
        }
    }
}

// ---------------- flash attention, mma.sync fp16, per (window, head) ----------------
// smem: K[384x32] 24576B | V[384x32] 24576B | Q[128x32] 8192B
#define ASM_K 0
#define ASM_V 24576
#define ASM_Q 49152
#define ATT_SMEM 57344

__global__ void __launch_bounds__(256)
attn_mma_kernel()
{
    extern __shared__ char sm[];
    const uint32_t sb = smem_u32(sm);
    const int w = blockIdx.x / NHEAD;
    const int h = blockIdx.x % NHEAD;
    const int tid = threadIdx.x, lane = tid & 31, wid = tid >> 5;
    const int gid = lane >> 2, tig = lane & 3;

    // zero ONLY pad rows 343..383 of K and V (41 rows x 4 chunks x 2 buffers)
    for (int i = tid; i < 41 * 4 * 2; i += 256) {
        int buf = i / 164;
        int j = i % 164;
        int row = 343 + (j >> 2), c = j & 3;
        ZERO16(sb + (buf ? ASM_V : ASM_K) + swz(row, c));
    }

    // stage K and V for this (window, head)
    {
        const __half* kp = g_KVf + (size_t)(w * NTOK) * C2 + h * HD;
        const __half* vp = kp + C_DIM;
        for (int i = tid; i < NTOK * 4; i += 256) {
            int row = i >> 2, c = i & 3;
            uint32_t so = swz(row, c);
            size_t go = (size_t)row * C2 + c * 8;
            cp16(sb + ASM_K + so, kp + go);
            cp16(sb + ASM_V + so, vp + go);
        }
        CP_COMMIT();
    }
    asm volatile("cp.async.wait_group 0;" ::: "memory");
    __syncthreads();

    const float scale = 0.17677669529663687f; // 1/sqrt(32)
    const float* bb = g_bias + (size_t)h * NTOK * BSTR;

    for (int qs = 0; qs < 3; qs++) {
        int q0 = qs * 128;
        // stage Q supertile (128 rows)
        {
            const __half* qp = g_Qf + ((size_t)(w * NTOK + q0)) * C_DIM + h * HD;
            for (int i = tid; i < 512; i += 256) {
                int row = i >> 2, c = i & 3;
                uint32_t so = sb + ASM_Q + swz(row, c);
                if (q0 + row < NTOK) cp16(so, qp + (size_t)row * C_DIM + c * 8);
                else ZERO16(so);
            }
            CP_COMMIT();
        }
        asm volatile("cp.async.wait_group 0;" ::: "memory");
        __syncthreads();

        // Q fragments (warp owns 16 rows)
        uint32_t qf[2][4];
#pragma unroll
        for (int ks = 0; ks < 2; ks++) {
            uint32_t row = wid * 16 + (lane & 15);
            uint32_t c = 2 * ks + (lane >> 4);
            LDMX4(qf[ks][0], qf[ks][1], qf[ks][2], qf[ks][3], sb + ASM_Q + swz(row, c));
        }
        __syncthreads();   // all warps done reading Q smem before next restage

        int qrow0 = q0 + wid * 16 + gid;
        int qrow1 = qrow0 + 8;
        bool rv0 = qrow0 < NTOK, rv1 = qrow1 < NTOK;
        float m0 = -1e30f, m1 = -1e30f, l0 = 0.f, l1 = 0.f;
        float oacc[4][4];
#pragma unroll
        for (int o = 0; o < 4; o++)
#pragma unroll
            for (int v = 0; v < 4; v++) oacc[o][v] = 0.f;

        for (int kt = 0; kt < 6; kt++) {
            int t0 = kt * 64;
            float sacc[8][4];
#pragma unroll
            for (int n = 0; n < 8; n++)
#pragma unroll
                for (int v = 0; v < 4; v++) sacc[n][v] = 0.f;

            // S = Q K^T
#pragma unroll
            for (int ks = 0; ks < 2; ks++) {
                uint32_t krow = t0 + (lane & 7);
                uint32_t kc = 2 * ks + ((lane >> 3) & 1);
                uint32_t kf[8][2];
#pragma unroll
                for (int nb = 0; nb < 8; nb++)
                    LDMX2(kf[nb][0], kf[nb][1], sb + ASM_K + swz(krow + nb * 8, kc));
#pragma unroll
                for (int nb = 0; nb < 8; nb++)
                    MMA16816(sacc[nb], qf[ks], kf[nb]);
            }

            // scale + bias + mask, row max
            float rmax0 = -1e30f, rmax1 = -1e30f;
#pragma unroll
            for (int nb = 0; nb < 8; nb++) {
                int col = t0 + nb * 8 + tig * 2;
                if (col < NTOK) {
                    bool c1 = (col + 1 < NTOK);
                    float2 b0 = rv0 ? *(const float2*)(bb + (size_t)qrow0 * BSTR + col)
                                    : make_float2(0.f, 0.f);
                    float2 b1 = rv1 ? *(const float2*)(bb + (size_t)qrow1 * BSTR + col)
                                    : make_float2(0.f, 0.f);
                    sacc[nb][0] = sacc[nb][0] * scale + b0.x;
                    sacc[nb][1] = c1 ? sacc[nb][1] * scale + b0.y : -1e30f;
                    sacc[nb][2] = sacc[nb][2] * scale + b1.x;
                    sacc[nb][3] = c1 ? sacc[nb][3] * scale + b1.y : -1e30f;
                } else {
                    sacc[nb][0] = sacc[nb][1] = sacc[nb][2] = sacc[nb][3] = -1e30f;
                }
                rmax0 = fmaxf(rmax0, fmaxf(sacc[nb][0], sacc[nb][1]));
                rmax1 = fmaxf(rmax1, fmaxf(sacc[nb][2], sacc[nb][3]));
            }
            rmax0 = fmaxf(rmax0, __shfl_xor_sync(0xffffffffu, rmax0, 1));
            rmax0 = fmaxf(rmax0, __shfl_xor_sync(0xffffffffu, rmax0, 2));
            rmax1 = fmaxf(rmax1, __shfl_xor_sync(0xffffffffu, rmax1, 1));
            rmax1 = fmaxf(rmax1, __shfl_xor_sync(0xffffffffu, rmax1, 2));

            float mn0 = fmaxf(m0, rmax0), mn1 = fmaxf(m1, rmax1);
            float sc0 = __expf(m0 - mn0), sc1 = __expf(m1 - mn1);
            m0 = mn0; m1 = mn1;

            float rs0 = 0.f, rs1 = 0.f;
#pragma unroll
            for (int nb = 0; nb < 8; nb++) {
                sacc[nb][0] = __expf(sacc[nb][0] - m0);
                sacc[nb][1] = __expf(sacc[nb][1] - m0);
                sacc[nb][2] = __expf(sacc[nb][2] - m1);
                sacc[nb][3] = __expf(sacc[nb][3] - m1);
                rs0 += sacc[nb][0] + sacc[nb][1];
                rs1 += sacc[nb][2] + sacc[nb][3];
            }
            rs0 += __shfl_xor_sync(0xffffffffu, rs0, 1);
            rs0 += __shfl_xor_sync(0xffffffffu, rs0, 2);
            rs1 += __shfl_xor_sync(0xffffffffu, rs1, 1);
            rs1 += __shfl_xor_sync(0xffffffffu, rs1, 2);
            l0 = l0 * sc0 + rs0;
            l1 = l1 * sc1 + rs1;
#pragma unroll
            for (int o = 0; o < 4; o++) {
                oacc[o][0] *= sc0; oacc[o][1] *= sc0;
                oacc[o][2] *= sc1; oacc[o][3] *= sc1;
            }

            // O += P V (P fp16 single)
#pragma unroll
            for (int ks2 = 0; ks2 < 4; ks2++) {
                float* f0 = sacc[2 * ks2];
                float* f1 = sacc[2 * ks2 + 1];
                uint32_t pa[4];
                pa[0] = packh(f0[0], f0[1]);
                pa[1] = packh(f0[2], f0[3]);
                pa[2] = packh(f1[0], f1[1]);
                pa[3] = packh(f1[2], f1[3]);
                uint32_t vrow = t0 + ks2 * 16 + (lane & 15);
                uint32_t bv[4][2];
#pragma unroll
                for (int onb = 0; onb < 4; onb++)
                    LDMX2T(bv[onb][0], bv[onb][1], sb + ASM_V + swz(vrow, onb));
#pragma unroll
                for (int onb = 0; onb < 4; onb++)
                    MMA16816(oacc[onb], pa, bv[onb]);
            }
        } // kt

        float inv0 = 1.f / l0, inv1 = 1.f / l1;
#pragma unroll
        for (int onb = 0; onb < 4; onb++) {
            int ch = h * HD + onb * 8 + tig * 2;
            if (rv0) {
                size_t base = ((size_t)(w * NTOK + qrow0)) * C_DIM + ch;
                *(uint32_t*)(g_Of + base) = packh(oacc[onb][0] * inv0, oacc[onb][1] * inv0);
            }
            if (rv1) {
                size_t base = ((size_t)(w * NTOK + qrow1)) * C_DIM + ch;
                *(uint32_t*)(g_Of + base) = packh(oacc[onb][2] * inv1, oacc[onb][3] * inv1);
            }
        }
    } // qs
}

// ---------------- LN2 -> Yf ----------------
__global__ void ln2_kernel(const float* __restrict__ g, const float* __restrict__ b)
{
    int l = blockIdx.x, tid = threadIdx.x;
    const float* row = g_X + (size_t)l * C_DIM;
    float xv[3];
    float s = 0.f, sq = 0.f;
#pragma unroll
    for (int t = 0; t < 3; t++) {
        int c = tid + t * 128;
        float x = row[c];
        xv[t] = x; s += x; sq += x * x;
    }
    __shared__ float red[4][2];
#pragma unroll
    for (int o = 16; o > 0; o >>= 1) {
        s  += __shfl_down_sync(0xffffffffu, s , o);
        sq += __shfl_down_sync(0xffffffffu, sq, o);
    }
    int warp = tid >> 5, lane = tid & 31;
    if (lane == 0) { red[warp][0] = s; red[warp][1] = sq; }
    __syncthreads();
    float S  = red[0][0]+red[1][0]+red[2][0]+red[3][0];
    float SQ = red[0][1]+red[1][1]+red[2][1]+red[3][1];
    const float inv = 1.f / (float)C_DIM;
    float m = S * inv;
    float rs = rsqrtf(SQ * inv - m * m + 1e-5f);
#pragma unroll
    for (int t = 0; t < 3; t++) {
        int c = tid + t * 128;
        g_Yf[(size_t)l * C_DIM + c] = __float2half((xv[t] - m) * rs * g[c] + b[c]);
    }
}

// ---------------- launch ----------------
extern "C" void kernel_launch(void* const* d_in, const int* in_sizes, int n_in,
                              void* d_out, int out_size)
{
    const float* skip = (const float*)d_in[0];
    const float* x_up = (const float*)d_in[1];
    int o = (n_in >= 18) ? 5 : 2;
    const float* ln1_g  = (const float*)d_in[o + 0];
    const float* ln1_b  = (const float*)d_in[o + 1];
    const float* kv_w   = (const float*)d_in[o + 2];
    const float* kv_b   = (const float*)d_in[o + 3];
    const float* rpb    = (const float*)d_in[o + 4];
    const float* proj_w = (const float*)d_in[o + 5];
    const float* proj_b = (const float*)d_in[o + 6];
    const float* ln2_g  = (const float*)d_in[o + 7];
    const float* ln2_b  = (const float*)d_in[o + 8];
    const float* mlp_w1 = (const float*)d_in[o + 9];
    const float* mlp_b1 = (const float*)d_in[o + 10];
    const float* mlp_w2 = (const float*)d_in[o + 11];
    const float* mlp_b2 = (const float*)d_in[o + 12];
    float* out = (float*)d_out;

    float* pX;
    __half *pSK, *pKV, *pO, *pY, *pH1, *pWkv, *pWpr, *pW1, *pW2;
    cudaGetSymbolAddress((void**)&pX,   g_X);
    cudaGetSymbolAddress((void**)&pSK,  g_SKf);
    cudaGetSymbolAddress((void**)&pKV,  g_KVf);
    cudaGetSymbolAddress((void**)&pO,   g_Of);
    cudaGetSymbolAddress((void**)&pY,   g_Yf);
    cudaGetSymbolAddress((void**)&pH1,  g_H1f);
    cudaGetSymbolAddress((void**)&pWkv, g_Wkv);
    cudaGetSymbolAddress((void**)&pWpr, g_Wpr);
    cudaGetSymbolAddress((void**)&pW1,  g_W1);
    cudaGetSymbolAddress((void**)&pW2,  g_W2);

    int gemm_smem = NSTG * STAGE;  // 48 KB
    cudaFuncSetAttribute(hmma_gemm<0>, cudaFuncAttributeMaxDynamicSharedMemorySize, gemm_smem);
    cudaFuncSetAttribute(hmma_gemm<1>, cudaFuncAttributeMaxDynamicSharedMemorySize, gemm_smem);
    cudaFuncSetAttribute(hmma_gemm<2>, cudaFuncAttributeMaxDynamicSharedMemorySize, gemm_smem);
    cudaFuncSetAttribute(hmma_gemm<3>, cudaFuncAttributeMaxDynamicSharedMemorySize, gemm_smem);
    cudaFuncSetAttribute(attn_mma_kernel, cudaFuncAttributeMaxDynamicSharedMemorySize, ATT_SMEM);

    const int MT = MPAD / GBM;  // 172

    add_ln1_kernel<<<L_TOK, 128>>>(skip, x_up, ln1_g, ln1_b);                   // 0
    bias_kernel<<<(NHEAD * NTOK * NTOK + 255) / 256, 256>>>(rpb);               // 1
    wprep_kernel<<<(C_DIM * C2 + 255) / 256, 256>>>(kv_w, pWkv, C_DIM, C2);     // 2
    wprep_kernel<<<(C_DIM * C_DIM + 255) / 256, 256>>>(proj_w, pWpr, C_DIM, C_DIM); // 3
    wprep_kernel<<<(C_DIM * C4 + 255) / 256, 256>>>(mlp_w1, pW1, C_DIM, C4);    // 4
    hmma_gemm<0><<<dim3(C2 / GBN, MT), 128, gemm_smem>>>(pSK, pWkv,             // 5 <- profiled
        kv_b, nullptr, pKV, nullptr, C_DIM, C2, L_TOK);
    attn_mma_kernel<<<NWIN * NHEAD, 256, ATT_SMEM>>>();                         // 6
    hmma_gemm<1><<<dim3(C_DIM / GBN, MT), 128, gemm_smem>>>(pO, pWpr,           // 7
        proj_b, pX, nullptr, nullptr, C_DIM, C_DIM, L_TOK);
    ln2_kernel<<<L_TOK, 128>>>(ln2_g, ln2_b);                                   // 8
    hmma_gemm<2><<<dim3(C4 / GBN, MT), 128, gemm_smem>>>(pY, pW1,               // 9
        mlp_b1, nullptr, pH1, nullptr, C_DIM, C4, L_TOK);
    wprep_kernel<<<(C4 * C_DIM + 255) / 256, 256>>>(mlp_w2, pW2, C4, C_DIM);    // 10
    hmma_gemm<3><<<dim3(C_DIM / GBN, MT), 128, gemm_smem>>>(pH1, pW2,           // 11
        mlp_b2, out, nullptr, pX, C4, C_DIM, L_TOK);
}